// round 1
// baseline (speedup 1.0000x reference)
#include <cuda_runtime.h>

#define CN 128
#define HN 256
#define TN 4
#define SN 57
#define PN 10
#define BK 16

// ---------------- scratch (device globals; no allocation) ----------------
__device__ float g_cf[CN*HN];          // cf (C,H)
__device__ float g_pg[CN*HN];          // pg (C,H)
__device__ float g_A [CN*HN];          // el factor A
__device__ float g_Bv[CN*HN];          // el factor B (+bel)
__device__ float g_el[CN*CN*HN];       // el (C*C, H)  16.8MB
__device__ float g_W3[2*HN*HN];        // packed W3 for both iters (512,256)
__device__ float g_E [CN*CN*2*HN];     // E (C*C, 512) 33.5MB
__device__ float g_U [CN*HN];
__device__ float g_V [CN*HN];
__device__ float g_x1[CN*HN];
__device__ float g_x2[CN*HN];
__device__ int   g_ok[CN];

__device__ __forceinline__ float lrelu(float x){ return x > 0.f ? x : 0.01f*x; }

__device__ __forceinline__ float2 fma2(float2 a, float2 b, float2 c) {
    unsigned long long au = *reinterpret_cast<unsigned long long*>(&a);
    unsigned long long bu = *reinterpret_cast<unsigned long long*>(&b);
    unsigned long long cu = *reinterpret_cast<unsigned long long*>(&c);
    unsigned long long du;
    asm("fma.rn.f32x2 %0, %1, %2, %3;" : "=l"(du) : "l"(au), "l"(bu), "l"(cu));
    return *reinterpret_cast<float2*>(&du);
}

// ---------------- 1. big GEMVs: cf and pg (32768 outs each, K=256) --------
__global__ void k_gemv_big(const float* __restrict__ psf, const float* __restrict__ Wp,
                           const float* __restrict__ bp,  const float* __restrict__ pgf,
                           const float* __restrict__ Wgp, const float* __restrict__ bgp) {
    __shared__ float sin_[HN];
    bool second = blockIdx.x >= 512;
    const float* in = second ? pgf : psf;
    const float* W  = second ? Wgp : Wp;
    const float* b  = second ? bgp : bp;
    float* out      = second ? g_pg : g_cf;
    int base = (blockIdx.x & 511) * 64;
    sin_[threadIdx.x] = in[threadIdx.x];
    __syncthreads();
    int warp = threadIdx.x >> 5, lane = threadIdx.x & 31;
    #pragma unroll
    for (int rr = 0; rr < 8; rr++) {
        int r = base + warp*8 + rr;
        const float* wr = W + (size_t)r * HN;
        float s = 0.f;
        #pragma unroll
        for (int q = 0; q < 8; q++) s += wr[lane + 32*q] * sin_[lane + 32*q];
        #pragma unroll
        for (int o = 16; o; o >>= 1) s += __shfl_down_sync(0xffffffffu, s, o);
        if (lane == 0) out[r] = lrelu(s + b[r]);
    }
}

// ---------------- 2. child_geo: GEMM row + groupnorm + lrelu --------------
__global__ void k_geo(const float* __restrict__ Wgc, const float* __restrict__ bgc,
                      const float* __restrict__ gw,  const float* __restrict__ gb,
                      float* __restrict__ outg) {
    int i = blockIdx.x, h = threadIdx.x;
    __shared__ float sx[HN], sy[HN], sm[32], sv[32];
    sx[h] = g_pg[i*HN + h];
    __syncthreads();
    const float* w = Wgc + (size_t)h * HN;
    float s = 0.f;
    #pragma unroll 8
    for (int k = 0; k < HN; k++) s += w[k]*sx[k];
    s += bgc[h];
    sy[h] = s;
    __syncthreads();
    if (h < 32) {
        float m = 0.f, v = 0.f;
        #pragma unroll
        for (int q = 0; q < 8; q++) { float y = sy[h*8+q]; m += y; v += y*y; }
        m *= 0.125f; v = v*0.125f - m*m;
        sm[h] = m; sv[h] = rsqrtf(v + 1e-5f);
    }
    __syncthreads();
    float xn = (s - sm[h>>3]) * sv[h>>3] * gw[h] + gb[h];
    outg[i*HN + h] = lrelu(xn);
}

// ---------------- 3. small heads: exists/sem/semins + node_ok -------------
__global__ void k_heads(const float* __restrict__ We,  const float* __restrict__ be,
                        const float* __restrict__ Ws,  const float* __restrict__ bs,
                        const float* __restrict__ Wsi, const float* __restrict__ bsi,
                        float* __restrict__ o_sem, float* __restrict__ o_semins,
                        float* __restrict__ o_exists) {
    int i = blockIdx.x, t = threadIdx.x;
    __shared__ float sx[HN];
    sx[t] = g_cf[i*HN + t];
    __syncthreads();
    if (t < SN) {
        const float* w = Ws + t*HN;
        float s = 0.f;
        for (int k = 0; k < HN; k++) s += w[k]*sx[k];
        o_sem[i*SN + t] = s + bs[t];
    } else if (t < SN + PN) {
        int p = t - SN;
        const float* w = Wsi + p*HN;
        float s = 0.f;
        for (int k = 0; k < HN; k++) s += w[k]*sx[k];
        o_semins[i*PN + p] = s + bsi[p];
    } else if (t == SN + PN) {
        float s = 0.f;
        for (int k = 0; k < HN; k++) s += We[k]*sx[k];
        s += be[0];
        o_exists[i] = s;
        g_ok[i] = (s > 0.f) ? 1 : 0;
    }
}

// ---------------- 4. el factors A, B --------------------------------------
__global__ void k_ab(const float* __restrict__ Wel, const float* __restrict__ bel) {
    int i = blockIdx.x, h = threadIdx.x;
    __shared__ float sx[HN];
    sx[h] = g_cf[i*HN + h];
    __syncthreads();
    const float* w = Wel + (size_t)h * (2*HN);
    float a = 0.f, b = 0.f;
    #pragma unroll 8
    for (int k = 0; k < HN; k++) { a += w[k]*sx[k]; b += w[HN+k]*sx[k]; }
    g_A [i*HN + h] = a;
    g_Bv[i*HN + h] = b + bel[h];
}

// ---------------- 5. el materialization + edge_logits ---------------------
__global__ void k_el(const float* __restrict__ Wee, const float* __restrict__ bee,
                     float* __restrict__ o_logits) {
    int j = blockIdx.x, i = blockIdx.y, h = threadIdx.x;
    float e = lrelu(g_A[i*HN + h] + g_Bv[j*HN + h]);
    int m = i*CN + j;
    g_el[(size_t)m*HN + h] = e;
    float p0 = e*Wee[h], p1 = e*Wee[HN+h], p2 = e*Wee[2*HN+h], p3 = e*Wee[3*HN+h];
    #pragma unroll
    for (int o = 16; o; o >>= 1) {
        p0 += __shfl_down_sync(0xffffffffu, p0, o);
        p1 += __shfl_down_sync(0xffffffffu, p1, o);
        p2 += __shfl_down_sync(0xffffffffu, p2, o);
        p3 += __shfl_down_sync(0xffffffffu, p3, o);
    }
    __shared__ float red[8][4];
    int warp = h >> 5, lane = h & 31;
    if (lane == 0) { red[warp][0]=p0; red[warp][1]=p1; red[warp][2]=p2; red[warp][3]=p3; }
    __syncthreads();
    if (h < 4) {
        float s = bee[h];
        #pragma unroll
        for (int w = 0; w < 8; w++) s += red[w][h];
        o_logits[m*4 + h] = s;
    }
}

// ---------------- 6. pack W3 (el-columns of Wne, both iters) --------------
__global__ void k_pack(const float* __restrict__ Wne) {
    int idx = blockIdx.x*256 + threadIdx.x;       // 0..131071
    int n = idx >> 8, k = idx & 255;
    int it = n >> 8, r = n & 255;
    g_W3[idx] = Wne[((size_t)it*HN + r)*772 + 512 + k];
}

// ---------------- 7. E = el(16384x256) @ W3^T(256x512), f32x2 FFMA2 -------
__global__ void __launch_bounds__(256, 2) k_gemm() {
    __shared__ float As[BK*128];   // [k][m]
    __shared__ float Bs[BK*128];   // [k][n]
    int tid = threadIdx.x;
    int bm = blockIdx.x, bn = blockIdx.y;
    int tx = tid & 15, ty = tid >> 4;
    const float* Ag = g_el + (size_t)bm*128*HN;
    const float* Bg = g_W3 + (size_t)bn*128*HN;

    float2 c[8][4];
    #pragma unroll
    for (int a = 0; a < 8; a++)
        #pragma unroll
        for (int q = 0; q < 4; q++) c[a][q] = make_float2(0.f, 0.f);

    for (int kb = 0; kb < HN; kb += BK) {
        #pragma unroll
        for (int q = 0; q < 2; q++) {
            int l = tid + 256*q;             // 0..511
            int m = l >> 2, c4 = l & 3;
            float4 v = *(const float4*)&Ag[(size_t)m*HN + kb + c4*4];
            As[(c4*4+0)*128 + m] = v.x;
            As[(c4*4+1)*128 + m] = v.y;
            As[(c4*4+2)*128 + m] = v.z;
            As[(c4*4+3)*128 + m] = v.w;
            float4 w = *(const float4*)&Bg[(size_t)m*HN + kb + c4*4];
            Bs[(c4*4+0)*128 + m] = w.x;
            Bs[(c4*4+1)*128 + m] = w.y;
            Bs[(c4*4+2)*128 + m] = w.z;
            Bs[(c4*4+3)*128 + m] = w.w;
        }
        __syncthreads();
        #pragma unroll
        for (int k = 0; k < BK; k++) {
            float2 b[4], a[4];
            #pragma unroll
            for (int q = 0; q < 4; q++)  b[q]  = *(const float2*)&Bs[k*128 + tx*2 + q*32];
            #pragma unroll
            for (int mi = 0; mi < 4; mi++) a[mi] = *(const float2*)&As[k*128 + ty*2 + mi*32];
            #pragma unroll
            for (int mi = 0; mi < 4; mi++) {
                float2 ax = make_float2(a[mi].x, a[mi].x);
                float2 ay = make_float2(a[mi].y, a[mi].y);
                #pragma unroll
                for (int q = 0; q < 4; q++) {
                    c[mi*2+0][q] = fma2(ax, b[q], c[mi*2+0][q]);
                    c[mi*2+1][q] = fma2(ay, b[q], c[mi*2+1][q]);
                }
            }
        }
        __syncthreads();
    }
    #pragma unroll
    for (int mi = 0; mi < 4; mi++) {
        #pragma unroll
        for (int r = 0; r < 2; r++) {
            int m = bm*128 + ty*2 + mi*32 + r;
            float* Erow = g_E + (size_t)m*512 + bn*128;
            #pragma unroll
            for (int q = 0; q < 4; q++)
                *(float2*)&Erow[tx*2 + q*32] = c[mi*2+r][q];
        }
    }
}

// ---------------- 8. per-iter U, V ----------------------------------------
__global__ void k_uv(const float* __restrict__ Wne, const float* __restrict__ bne, int it) {
    int i = blockIdx.x, h = threadIdx.x;
    const float* xin = (it == 0) ? g_cf : g_x1;
    __shared__ float sx[HN];
    sx[h] = xin[i*HN + h];
    __syncthreads();
    const float* w = Wne + ((size_t)it*HN + h)*772;
    float u = 0.f, v = 0.f;
    #pragma unroll 8
    for (int k = 0; k < HN; k++) { u += w[k]*sx[k]; v += w[HN+k]*sx[k]; }
    g_U[i*HN + h] = u + bne[it*HN + h];
    g_V[i*HN + h] = v;
}

// ---------------- 9. masked max-reduction over (j,t) ----------------------
__global__ void k_reduce(const float* __restrict__ o_logits,
                         const float* __restrict__ Wne, int it) {
    int i = blockIdx.x, h = threadIdx.x;
    float* xout = (it == 0) ? g_x1 : g_x2;
    __shared__ float slog[CN*TN];
    __shared__ int sok[CN];
    #pragma unroll
    for (int l = h; l < CN*TN; l += 256) slog[l] = o_logits[i*CN*TN + l];
    if (h < CN) sok[h] = g_ok[h];
    __syncthreads();
    if (!g_ok[i]) { xout[i*HN + h] = 0.f; return; }
    const float* wr = Wne + ((size_t)it*HN + h)*772 + 768;
    float w40 = wr[0], w41 = wr[1], w42 = wr[2], w43 = wr[3];
    float uh = g_U[i*HN + h];
    const float* Ep = g_E + (size_t)i*CN*512 + it*HN + h;
    float acc = -__int_as_float(0x7f800000);  // -inf
    for (int j = 0; j < CN; j++) {
        if (!sok[j]) continue;
        float l0 = slog[j*4+0], l1 = slog[j*4+1], l2 = slog[j*4+2], l3 = slog[j*4+3];
        bool any = false; float best = -3.4e38f;
        if (l0 > 0.f) { best = l0*w40; any = true; }
        if (l1 > 0.f) { float z = l1*w41; best = any ? fmaxf(best, z) : z; any = true; }
        if (l2 > 0.f) { float z = l2*w42; best = any ? fmaxf(best, z) : z; any = true; }
        if (l3 > 0.f) { float z = l3*w43; best = any ? fmaxf(best, z) : z; any = true; }
        if (!any) continue;
        float z = uh + g_V[j*HN + h] + Ep[(size_t)j*512] + best;
        acc = fmaxf(acc, z);
    }
    xout[i*HN + h] = fmaxf(acc, 0.f);   // == max(0, lrelu(max z)) incl. empty case
}

// ---------------- 10. final head: cat -> ch -> child ----------------------
__global__ void k_head(const float* __restrict__ Wc,  const float* __restrict__ bc,
                       const float* __restrict__ Wc2, const float* __restrict__ bc2,
                       float* __restrict__ o_child) {
    int i = blockIdx.x, h = threadIdx.x;
    __shared__ float scat[3*HN];
    __shared__ float sch[HN];
    scat[h]        = g_cf[i*HN + h];
    scat[HN + h]   = g_x1[i*HN + h];
    scat[2*HN + h] = g_x2[i*HN + h];
    __syncthreads();
    const float* w = Wc + (size_t)h * (3*HN);
    float s = 0.f;
    #pragma unroll 8
    for (int k = 0; k < 3*HN; k++) s += w[k]*scat[k];
    sch[h] = lrelu(s + bc[h]);
    __syncthreads();
    const float* w2 = Wc2 + (size_t)h * HN;
    float s2 = 0.f;
    #pragma unroll 8
    for (int k = 0; k < HN; k++) s2 += w2[k]*sch[k];
    o_child[i*HN + h] = lrelu(s2 + bc2[h]);
}

// ---------------- launch ---------------------------------------------------
extern "C" void kernel_launch(void* const* d_in, const int* in_sizes, int n_in,
                              void* d_out, int out_size) {
    const float* psf = (const float*)d_in[0];
    const float* pgf = (const float*)d_in[1];
    const float* Wp  = (const float*)d_in[2];
    const float* bp  = (const float*)d_in[3];
    const float* We  = (const float*)d_in[4];
    const float* be  = (const float*)d_in[5];
    const float* Ws  = (const float*)d_in[6];
    const float* bs  = (const float*)d_in[7];
    const float* Wsi = (const float*)d_in[8];
    const float* bsi = (const float*)d_in[9];
    const float* Wel = (const float*)d_in[10];
    const float* bel = (const float*)d_in[11];
    const float* Wee = (const float*)d_in[12];
    const float* bee = (const float*)d_in[13];
    const float* Wne = (const float*)d_in[14];
    const float* bne = (const float*)d_in[15];
    const float* Wc  = (const float*)d_in[16];
    const float* bc  = (const float*)d_in[17];
    const float* Wc2 = (const float*)d_in[18];
    const float* bc2 = (const float*)d_in[19];
    const float* Wgc = (const float*)d_in[20];
    const float* bgc = (const float*)d_in[21];
    const float* Wgp = (const float*)d_in[22];
    const float* bgp = (const float*)d_in[23];
    const float* gw  = (const float*)d_in[24];
    const float* gb  = (const float*)d_in[25];

    float* out       = (float*)d_out;
    float* o_child   = out;                    // 32768
    float* o_geo     = out + 32768;            // 32768
    float* o_sem     = out + 65536;            // 7296
    float* o_semins  = out + 72832;            // 1280
    float* o_exists  = out + 74112;            // 128
    float* o_logits  = out + 74240;            // 65536

    k_gemv_big<<<1024, 256>>>(psf, Wp, bp, pgf, Wgp, bgp);
    k_geo<<<CN, 256>>>(Wgc, bgc, gw, gb, o_geo);
    k_heads<<<CN, 256>>>(We, be, Ws, bs, Wsi, bsi, o_sem, o_semins, o_exists);
    k_ab<<<CN, 256>>>(Wel, bel);
    k_el<<<dim3(CN, CN), 256>>>(Wee, bee, o_logits);
    k_pack<<<512, 256>>>(Wne);
    k_gemm<<<dim3(128, 4), 256>>>();
    k_uv<<<CN, 256>>>(Wne, bne, 0);
    k_reduce<<<CN, 256>>>(o_logits, Wne, 0);
    k_uv<<<CN, 256>>>(Wne, bne, 1);
    k_reduce<<<CN, 256>>>(o_logits, Wne, 1);
    k_head<<<CN, 256>>>(Wc, bc, Wc2, bc2, o_child);
}

// round 2
// speedup vs baseline: 1.6985x; 1.6985x over previous
#include <cuda_runtime.h>

#define CN 128
#define HN 256
#define TN 4
#define SN 57
#define PN 10
#define BK 16

// ---------------- scratch (device globals; no allocation) ----------------
__device__ float g_cf[CN*HN];          // cf (C,H)
__device__ float g_pg[CN*HN];          // pg (C,H)
__device__ float g_AB[CN*2*HN];        // [A | B+bel]  (C,512)
__device__ float g_gy[CN*HN];          // geo pre-GN
__device__ float g_el[CN*CN*HN];       // el (C*C, H)  16.8MB
__device__ float g_E [CN*CN*2*HN];     // E (C*C, 512) 33.5MB
__device__ float g_UV[CN*2*HN];        // [U+bne | V] (C,512)
__device__ float g_ch[CN*HN];
__device__ float g_x1[CN*HN];
__device__ float g_x2[CN*HN];
__device__ int   g_ok[CN];

__device__ __forceinline__ float lrelu(float x){ return x > 0.f ? x : 0.01f*x; }

__device__ __forceinline__ float2 fma2(float2 a, float2 b, float2 c) {
    unsigned long long au = *reinterpret_cast<unsigned long long*>(&a);
    unsigned long long bu = *reinterpret_cast<unsigned long long*>(&b);
    unsigned long long cu = *reinterpret_cast<unsigned long long*>(&c);
    unsigned long long du;
    asm("fma.rn.f32x2 %0, %1, %2, %3;" : "=l"(du) : "l"(au), "l"(bu), "l"(cu));
    return *reinterpret_cast<float2*>(&du);
}

// ---------------- 1. big GEMVs: cf and pg (32768 outs each, K=256) --------
__global__ void k_gemv_big(const float* __restrict__ psf, const float* __restrict__ Wp,
                           const float* __restrict__ bp,  const float* __restrict__ pgf,
                           const float* __restrict__ Wgp, const float* __restrict__ bgp) {
    __shared__ float sin_[HN];
    bool second = blockIdx.x >= 512;
    const float* in = second ? pgf : psf;
    const float* W  = second ? Wgp : Wp;
    const float* b  = second ? bgp : bp;
    float* out      = second ? g_pg : g_cf;
    int base = (blockIdx.x & 511) * 64;
    sin_[threadIdx.x] = in[threadIdx.x];
    __syncthreads();
    int warp = threadIdx.x >> 5, lane = threadIdx.x & 31;
    #pragma unroll
    for (int rr = 0; rr < 8; rr++) {
        int r = base + warp*8 + rr;
        const float* wr = W + (size_t)r * HN;
        float s = 0.f;
        #pragma unroll
        for (int q = 0; q < 8; q++) s += wr[lane + 32*q] * sin_[lane + 32*q];
        #pragma unroll
        for (int o = 16; o; o >>= 1) s += __shfl_down_sync(0xffffffffu, s, o);
        if (lane == 0) out[r] = lrelu(s + b[r]);
    }
}

// ---------------- 2. generic tiled 32x32x32 SGEMM, M=128 ------------------
// MODE 0: AB   X=g_cf  W=Wel rows (a:h*512 | b:(h)*512+256), bias bel on n>=256 -> g_AB  N=512
// MODE 1: GEO  X=g_pg  W=Wgc(256,256), bias bgc -> g_gy                             N=256
// MODE 2: UV   X=(it?g_x1:g_cf) W=Wne rows (it*256+n&255)*772 (+256 for V), bias bne on n<256 -> g_UV  N=512
// MODE 3: HEAD1 X=[cf|x1|x2] K=768 W=Wc(256,768), bias bc, lrelu -> g_ch            N=256
// MODE 4: HEAD2 X=g_ch W=Wc2(256,256), bias bc2, lrelu -> out                       N=256
template<int MODE>
__global__ void __launch_bounds__(256) k_sgemm(const float* __restrict__ W,
                                               const float* __restrict__ b1,
                                               float* __restrict__ out, int it) {
    constexpr int K = (MODE == 3) ? 768 : 256;
    __shared__ float Xs[32][33];
    __shared__ float Ws[32][33];
    int tid = threadIdx.x;
    int bn = blockIdx.x, bm = blockIdx.y;
    int r  = tid >> 3, c4 = (tid & 7) * 4;
    int tx = tid & 15, ty = tid >> 4;
    int m0 = bm*32 + r;
    int n0 = bn*32 + r;

    const float* wrow;
    if      (MODE == 0) wrow = W + (n0 < 256 ? (size_t)n0*512 : (size_t)(n0-256)*512 + 256);
    else if (MODE == 1) wrow = W + (size_t)n0*256;
    else if (MODE == 2) wrow = W + ((size_t)it*256 + (n0 & 255))*772 + (n0 >= 256 ? 256 : 0);
    else if (MODE == 3) wrow = W + (size_t)n0*768;
    else                wrow = W + (size_t)n0*256;

    const float* Xbase;
    if      (MODE == 0) Xbase = g_cf;
    else if (MODE == 1) Xbase = g_pg;
    else if (MODE == 2) Xbase = it ? g_x1 : g_cf;
    else if (MODE == 4) Xbase = g_ch;
    else                Xbase = g_cf;   // MODE 3: per-tile select below

    float a00 = 0.f, a01 = 0.f, a10 = 0.f, a11 = 0.f;

    for (int kb = 0; kb < K; kb += 32) {
        const float* xptr;
        if (MODE == 3) {
            int g = kb + c4;
            const float* src = (g < 256) ? g_cf : (g < 512 ? g_x1 : g_x2);
            xptr = src + (size_t)m0*256 + (g & 255);
        } else {
            xptr = Xbase + (size_t)m0*256 + kb + c4;
        }
        float4 xv = *(const float4*)xptr;
        Xs[c4+0][r] = xv.x; Xs[c4+1][r] = xv.y; Xs[c4+2][r] = xv.z; Xs[c4+3][r] = xv.w;
        float4 wv = *(const float4*)(wrow + kb + c4);
        Ws[c4+0][r] = wv.x; Ws[c4+1][r] = wv.y; Ws[c4+2][r] = wv.z; Ws[c4+3][r] = wv.w;
        __syncthreads();
        #pragma unroll
        for (int k = 0; k < 32; k++) {
            float ax = Xs[k][ty*2], ay = Xs[k][ty*2+1];
            float bx = Ws[k][tx*2], by = Ws[k][tx*2+1];
            a00 += ax*bx; a01 += ax*by;
            a10 += ay*bx; a11 += ay*by;
        }
        __syncthreads();
    }

    int m = bm*32 + ty*2, n = bn*32 + tx*2;
    float accs[2][2] = {{a00, a01}, {a10, a11}};
    #pragma unroll
    for (int mi = 0; mi < 2; mi++) {
        #pragma unroll
        for (int ni = 0; ni < 2; ni++) {
            int mm = m + mi, nn = n + ni;
            float v = accs[mi][ni];
            if      (MODE == 0) g_AB[mm*512 + nn] = (nn >= 256) ? v + b1[nn-256] : v;
            else if (MODE == 1) g_gy[mm*256 + nn] = v + b1[nn];
            else if (MODE == 2) g_UV[mm*512 + nn] = (nn < 256) ? v + b1[it*256 + nn] : v;
            else if (MODE == 3) g_ch[mm*256 + nn] = lrelu(v + b1[nn]);
            else                out [mm*256 + nn] = lrelu(v + b1[nn]);
        }
    }
}

// ---------------- 3. groupnorm + lrelu epilogue for geo --------------------
__global__ void k_gn(const float* __restrict__ gw, const float* __restrict__ gb,
                     float* __restrict__ outg) {
    int i = blockIdx.x, h = threadIdx.x;
    __shared__ float sy[HN], sm[32], sv[32];
    float s = g_gy[i*HN + h];
    sy[h] = s;
    __syncthreads();
    if (h < 32) {
        float m = 0.f, v = 0.f;
        #pragma unroll
        for (int q = 0; q < 8; q++) { float y = sy[h*8+q]; m += y; v += y*y; }
        m *= 0.125f; v = v*0.125f - m*m;
        sm[h] = m; sv[h] = rsqrtf(v + 1e-5f);
    }
    __syncthreads();
    float xn = (s - sm[h>>3]) * sv[h>>3] * gw[h] + gb[h];
    outg[i*HN + h] = lrelu(xn);
}

// ---------------- 4. small heads: warp-per-output, coalesced ---------------
__global__ void k_heads(const float* __restrict__ We,  const float* __restrict__ be,
                        const float* __restrict__ Ws,  const float* __restrict__ bs,
                        const float* __restrict__ Wsi, const float* __restrict__ bsi,
                        float* __restrict__ o_sem, float* __restrict__ o_semins,
                        float* __restrict__ o_exists) {
    int i = blockIdx.x;
    int lane = threadIdx.x & 31, warp = threadIdx.x >> 5;
    float4 x0 = *(const float4*)&g_cf[i*HN + lane*4];
    float4 x1 = *(const float4*)&g_cf[i*HN + 128 + lane*4];
    for (int o = warp; o < SN + PN + 1; o += 8) {
        const float* w; float bias;
        if (o < SN)           { w = Ws  + o*HN;       bias = bs[o]; }
        else if (o < SN + PN) { w = Wsi + (o-SN)*HN;  bias = bsi[o-SN]; }
        else                  { w = We;               bias = be[0]; }
        float4 w0 = *(const float4*)&w[lane*4];
        float4 w1 = *(const float4*)&w[128 + lane*4];
        float s = w0.x*x0.x + w0.y*x0.y + w0.z*x0.z + w0.w*x0.w
                + w1.x*x1.x + w1.y*x1.y + w1.z*x1.z + w1.w*x1.w;
        #pragma unroll
        for (int q = 16; q; q >>= 1) s += __shfl_xor_sync(0xffffffffu, s, q);
        if (lane == 0) {
            s += bias;
            if (o < SN)           o_sem[i*SN + o] = s;
            else if (o < SN + PN) o_semins[i*PN + (o-SN)] = s;
            else { o_exists[i] = s; g_ok[i] = (s > 0.f) ? 1 : 0; }
        }
    }
}

// ---------------- 5. el materialization + edge_logits ---------------------
__global__ void k_el(const float* __restrict__ Wee, const float* __restrict__ bee,
                     float* __restrict__ o_logits) {
    int j = blockIdx.x, i = blockIdx.y, h = threadIdx.x;
    float e = lrelu(g_AB[i*512 + h] + g_AB[j*512 + 256 + h]);
    int m = i*CN + j;
    g_el[(size_t)m*HN + h] = e;
    float p0 = e*Wee[h], p1 = e*Wee[HN+h], p2 = e*Wee[2*HN+h], p3 = e*Wee[3*HN+h];
    #pragma unroll
    for (int o = 16; o; o >>= 1) {
        p0 += __shfl_down_sync(0xffffffffu, p0, o);
        p1 += __shfl_down_sync(0xffffffffu, p1, o);
        p2 += __shfl_down_sync(0xffffffffu, p2, o);
        p3 += __shfl_down_sync(0xffffffffu, p3, o);
    }
    __shared__ float red[8][4];
    int warp = h >> 5, lane = h & 31;
    if (lane == 0) { red[warp][0]=p0; red[warp][1]=p1; red[warp][2]=p2; red[warp][3]=p3; }
    __syncthreads();
    if (h < 4) {
        float s = bee[h];
        #pragma unroll
        for (int w = 0; w < 8; w++) s += red[w][h];
        o_logits[m*4 + h] = s;
    }
}

// ---------------- 6. E = el(16384x256) @ W3^T(256x512), f32x2 FFMA2 -------
// W3 row n (n in [0,512)) = Wne[n*772 + 512 .. +768)  (it = n>>8 folded in)
__global__ void __launch_bounds__(256, 2) k_gemm(const float* __restrict__ Wne) {
    __shared__ float As[BK*128];   // [k][m]
    __shared__ float Bs[BK*128];   // [k][n]
    int tid = threadIdx.x;
    int bm = blockIdx.x, bn = blockIdx.y;
    int tx = tid & 15, ty = tid >> 4;
    const float* Ag = g_el + (size_t)bm*128*HN;

    float2 c[8][4];
    #pragma unroll
    for (int a = 0; a < 8; a++)
        #pragma unroll
        for (int q = 0; q < 4; q++) c[a][q] = make_float2(0.f, 0.f);

    for (int kb = 0; kb < HN; kb += BK) {
        #pragma unroll
        for (int q = 0; q < 2; q++) {
            int l = tid + 256*q;             // 0..511
            int m = l >> 2, c4 = l & 3;
            float4 v = *(const float4*)&Ag[(size_t)m*HN + kb + c4*4];
            As[(c4*4+0)*128 + m] = v.x;
            As[(c4*4+1)*128 + m] = v.y;
            As[(c4*4+2)*128 + m] = v.z;
            As[(c4*4+3)*128 + m] = v.w;
            int ng = bn*128 + m;
            float4 w = *(const float4*)&Wne[(size_t)ng*772 + 512 + kb + c4*4];
            Bs[(c4*4+0)*128 + m] = w.x;
            Bs[(c4*4+1)*128 + m] = w.y;
            Bs[(c4*4+2)*128 + m] = w.z;
            Bs[(c4*4+3)*128 + m] = w.w;
        }
        __syncthreads();
        #pragma unroll
        for (int k = 0; k < BK; k++) {
            float2 b[4], a[4];
            #pragma unroll
            for (int q = 0; q < 4; q++)  b[q]  = *(const float2*)&Bs[k*128 + tx*2 + q*32];
            #pragma unroll
            for (int mi = 0; mi < 4; mi++) a[mi] = *(const float2*)&As[k*128 + ty*2 + mi*32];
            #pragma unroll
            for (int mi = 0; mi < 4; mi++) {
                float2 ax = make_float2(a[mi].x, a[mi].x);
                float2 ay = make_float2(a[mi].y, a[mi].y);
                #pragma unroll
                for (int q = 0; q < 4; q++) {
                    c[mi*2+0][q] = fma2(ax, b[q], c[mi*2+0][q]);
                    c[mi*2+1][q] = fma2(ay, b[q], c[mi*2+1][q]);
                }
            }
        }
        __syncthreads();
    }
    #pragma unroll
    for (int mi = 0; mi < 4; mi++) {
        #pragma unroll
        for (int r = 0; r < 2; r++) {
            int m = bm*128 + ty*2 + mi*32 + r;
            float* Erow = g_E + (size_t)m*512 + bn*128;
            #pragma unroll
            for (int q = 0; q < 4; q++)
                *(float2*)&Erow[tx*2 + q*32] = c[mi*2+r][q];
        }
    }
}

// ---------------- 7. masked max-reduction over (j,t) ----------------------
__global__ void k_reduce(const float* __restrict__ o_logits,
                         const float* __restrict__ Wne, int it) {
    int i = blockIdx.x, h = threadIdx.x;
    float* xout = (it == 0) ? g_x1 : g_x2;
    __shared__ float slog[CN*TN];
    __shared__ int sok[CN];
    #pragma unroll
    for (int l = h; l < CN*TN; l += 256) slog[l] = o_logits[i*CN*TN + l];
    if (h < CN) sok[h] = g_ok[h];
    __syncthreads();
    if (!g_ok[i]) { xout[i*HN + h] = 0.f; return; }
    const float* wr = Wne + ((size_t)it*HN + h)*772 + 768;
    float w40 = wr[0], w41 = wr[1], w42 = wr[2], w43 = wr[3];
    float uh = g_UV[i*512 + h];
    const float* Ep = g_E + (size_t)i*CN*512 + it*HN + h;
    float acc = -__int_as_float(0x7f800000);  // -inf
    for (int j = 0; j < CN; j++) {
        if (!sok[j]) continue;
        float l0 = slog[j*4+0], l1 = slog[j*4+1], l2 = slog[j*4+2], l3 = slog[j*4+3];
        bool any = false; float best = -3.4e38f;
        if (l0 > 0.f) { best = l0*w40; any = true; }
        if (l1 > 0.f) { float z = l1*w41; best = any ? fmaxf(best, z) : z; any = true; }
        if (l2 > 0.f) { float z = l2*w42; best = any ? fmaxf(best, z) : z; any = true; }
        if (l3 > 0.f) { float z = l3*w43; best = any ? fmaxf(best, z) : z; any = true; }
        if (!any) continue;
        float z = uh + g_UV[j*512 + 256 + h] + Ep[(size_t)j*512] + best;
        acc = fmaxf(acc, z);
    }
    xout[i*HN + h] = fmaxf(acc, 0.f);
}

// ---------------- launch ---------------------------------------------------
extern "C" void kernel_launch(void* const* d_in, const int* in_sizes, int n_in,
                              void* d_out, int out_size) {
    const float* psf = (const float*)d_in[0];
    const float* pgf = (const float*)d_in[1];
    const float* Wp  = (const float*)d_in[2];
    const float* bp  = (const float*)d_in[3];
    const float* We  = (const float*)d_in[4];
    const float* be  = (const float*)d_in[5];
    const float* Ws  = (const float*)d_in[6];
    const float* bs  = (const float*)d_in[7];
    const float* Wsi = (const float*)d_in[8];
    const float* bsi = (const float*)d_in[9];
    const float* Wel = (const float*)d_in[10];
    const float* bel = (const float*)d_in[11];
    const float* Wee = (const float*)d_in[12];
    const float* bee = (const float*)d_in[13];
    const float* Wne = (const float*)d_in[14];
    const float* bne = (const float*)d_in[15];
    const float* Wc  = (const float*)d_in[16];
    const float* bc  = (const float*)d_in[17];
    const float* Wc2 = (const float*)d_in[18];
    const float* bc2 = (const float*)d_in[19];
    const float* Wgc = (const float*)d_in[20];
    const float* bgc = (const float*)d_in[21];
    const float* Wgp = (const float*)d_in[22];
    const float* bgp = (const float*)d_in[23];
    const float* gw  = (const float*)d_in[24];
    const float* gb  = (const float*)d_in[25];

    float* out       = (float*)d_out;
    float* o_child   = out;                    // 32768
    float* o_geo     = out + 32768;            // 32768
    float* o_sem     = out + 65536;            // 7296
    float* o_semins  = out + 72832;            // 1280
    float* o_exists  = out + 74112;            // 128
    float* o_logits  = out + 74240;            // 65536

    k_gemv_big<<<1024, 256>>>(psf, Wp, bp, pgf, Wgp, bgp);
    k_sgemm<1><<<dim3(8, 4), 256>>>(Wgc, bgc, nullptr, 0);       // geo GEMM
    k_gn<<<CN, 256>>>(gw, gb, o_geo);
    k_heads<<<CN, 256>>>(We, be, Ws, bs, Wsi, bsi, o_sem, o_semins, o_exists);
    k_sgemm<0><<<dim3(16, 4), 256>>>(Wel, bel, nullptr, 0);      // A|B
    k_el<<<dim3(CN, CN), 256>>>(Wee, bee, o_logits);
    k_gemm<<<dim3(128, 4), 256>>>(Wne);                          // E
    k_sgemm<2><<<dim3(16, 4), 256>>>(Wne, bne, nullptr, 0);      // U|V it=0
    k_reduce<<<CN, 256>>>(o_logits, Wne, 0);
    k_sgemm<2><<<dim3(16, 4), 256>>>(Wne, bne, nullptr, 1);      // U|V it=1
    k_reduce<<<CN, 256>>>(o_logits, Wne, 1);
    k_sgemm<3><<<dim3(8, 4), 256>>>(Wc, bc, nullptr, 0);         // head1
    k_sgemm<4><<<dim3(8, 4), 256>>>(Wc2, bc2, o_child, 0);       // head2
}

// round 3
// speedup vs baseline: 1.9229x; 1.1321x over previous
#include <cuda_runtime.h>

#define CN 128
#define HN 256
#define TN 4
#define SN 57
#define PN 10
#define BK 16

// ---------------- scratch (device globals; no allocation) ----------------
__device__ float g_cf[CN*HN];          // cf (C,H)
__device__ float g_pg[CN*HN];          // pg (C,H)
__device__ float g_AB[CN*2*HN];        // [A | B+bel]  (C,512)
__device__ float g_gy[CN*HN];          // geo pre-GN
__device__ float g_el[CN*CN*HN];       // el (C*C, H)  16.8MB
__device__ float g_E [CN*CN*2*HN];     // E (C*C, 512) 33.5MB
__device__ float g_UV[CN*2*HN];        // [U+bne | V] (C,512)
__device__ float g_ch[CN*HN];
__device__ float g_x1[CN*HN];
__device__ float g_x2[CN*HN];
__device__ int   g_ok[CN];

__device__ __forceinline__ float lrelu(float x){ return x > 0.f ? x : 0.01f*x; }

__device__ __forceinline__ float2 fma2(float2 a, float2 b, float2 c) {
    unsigned long long au = *reinterpret_cast<unsigned long long*>(&a);
    unsigned long long bu = *reinterpret_cast<unsigned long long*>(&b);
    unsigned long long cu = *reinterpret_cast<unsigned long long*>(&c);
    unsigned long long du;
    asm("fma.rn.f32x2 %0, %1, %2, %3;" : "=l"(du) : "l"(au), "l"(bu), "l"(cu));
    return *reinterpret_cast<float2*>(&du);
}

// ---------------- 1. big GEMVs: cf and pg (32768 outs each, K=256) --------
__global__ void k_gemv_big(const float* __restrict__ psf, const float* __restrict__ Wp,
                           const float* __restrict__ bp,  const float* __restrict__ pgf,
                           const float* __restrict__ Wgp, const float* __restrict__ bgp) {
    __shared__ float sin_[HN];
    bool second = blockIdx.x >= 512;
    const float* in = second ? pgf : psf;
    const float* W  = second ? Wgp : Wp;
    const float* b  = second ? bgp : bp;
    float* out      = second ? g_pg : g_cf;
    int base = (blockIdx.x & 511) * 64;
    sin_[threadIdx.x] = in[threadIdx.x];
    __syncthreads();
    int warp = threadIdx.x >> 5, lane = threadIdx.x & 31;
    #pragma unroll
    for (int rr = 0; rr < 8; rr++) {
        int r = base + warp*8 + rr;
        const float* wr = W + (size_t)r * HN;
        float s = 0.f;
        #pragma unroll
        for (int q = 0; q < 2; q++) {
            float4 wv = *(const float4*)&wr[lane*4 + 128*q];
            float4 xv = *(const float4*)&sin_[lane*4 + 128*q];
            s += wv.x*xv.x + wv.y*xv.y + wv.z*xv.z + wv.w*xv.w;
        }
        #pragma unroll
        for (int o = 16; o; o >>= 1) s += __shfl_down_sync(0xffffffffu, s, o);
        if (lane == 0) out[r] = lrelu(s + b[r]);
    }
}

// ---------------- 2. generic tiled 32x32x32 SGEMM, M=128, double-buffered --
template<int MODE>
__global__ void __launch_bounds__(256) k_sgemm(const float* __restrict__ W,
                                               const float* __restrict__ b1,
                                               float* __restrict__ out, int it) {
    constexpr int K  = (MODE == 3) ? 768 : 256;
    constexpr int NT = K / 32;
    __shared__ float Xs[2][32][33];
    __shared__ float Ws[2][32][33];
    int tid = threadIdx.x;
    int bn = blockIdx.x, bm = blockIdx.y;
    int r  = tid >> 3, c4 = (tid & 7) * 4;
    int tx = tid & 15, ty = tid >> 4;
    int m0 = bm*32 + r;
    int n0 = bn*32 + r;

    const float* wrow;
    if      (MODE == 0) wrow = W + (n0 < 256 ? (size_t)n0*512 : (size_t)(n0-256)*512 + 256);
    else if (MODE == 1) wrow = W + (size_t)n0*256;
    else if (MODE == 2) wrow = W + ((size_t)it*256 + (n0 & 255))*772 + (n0 >= 256 ? 256 : 0);
    else if (MODE == 3) wrow = W + (size_t)n0*768;
    else                wrow = W + (size_t)n0*256;

    const float* Xbase;
    if      (MODE == 0) Xbase = g_cf;
    else if (MODE == 1) Xbase = g_pg;
    else if (MODE == 2) Xbase = it ? g_x1 : g_cf;
    else if (MODE == 4) Xbase = g_ch;
    else                Xbase = g_cf;

    auto loadX = [&](int kb) -> float4 {
        if (MODE == 3) {
            int g = kb + c4;
            const float* src = (g < 256) ? g_cf : (g < 512 ? g_x1 : g_x2);
            return *(const float4*)(src + (size_t)m0*256 + (g & 255));
        }
        return *(const float4*)(Xbase + (size_t)m0*256 + kb + c4);
    };

    float4 xv = loadX(0);
    float4 wv = *(const float4*)(wrow + c4);
    float a00 = 0.f, a01 = 0.f, a10 = 0.f, a11 = 0.f;

    for (int t = 0; t < NT; t++) {
        int cur = t & 1;
        Xs[cur][c4+0][r] = xv.x; Xs[cur][c4+1][r] = xv.y;
        Xs[cur][c4+2][r] = xv.z; Xs[cur][c4+3][r] = xv.w;
        Ws[cur][c4+0][r] = wv.x; Ws[cur][c4+1][r] = wv.y;
        Ws[cur][c4+2][r] = wv.z; Ws[cur][c4+3][r] = wv.w;
        __syncthreads();
        if (t + 1 < NT) {
            xv = loadX((t+1)*32);
            wv = *(const float4*)(wrow + (t+1)*32 + c4);
        }
        #pragma unroll
        for (int k = 0; k < 32; k++) {
            float ax = Xs[cur][k][ty*2], ay = Xs[cur][k][ty*2+1];
            float bx = Ws[cur][k][tx*2], by = Ws[cur][k][tx*2+1];
            a00 += ax*bx; a01 += ax*by;
            a10 += ay*bx; a11 += ay*by;
        }
    }

    int m = bm*32 + ty*2, n = bn*32 + tx*2;
    float accs[2][2] = {{a00, a01}, {a10, a11}};
    #pragma unroll
    for (int mi = 0; mi < 2; mi++) {
        #pragma unroll
        for (int ni = 0; ni < 2; ni++) {
            int mm = m + mi, nn = n + ni;
            float v = accs[mi][ni];
            if      (MODE == 0) g_AB[mm*512 + nn] = (nn >= 256) ? v + b1[nn-256] : v;
            else if (MODE == 1) g_gy[mm*256 + nn] = v + b1[nn];
            else if (MODE == 2) g_UV[mm*512 + nn] = (nn < 256) ? v + b1[it*256 + nn] : v;
            else if (MODE == 3) g_ch[mm*256 + nn] = lrelu(v + b1[nn]);
            else                out [mm*256 + nn] = lrelu(v + b1[nn]);
        }
    }
}

// ---------------- 3. groupnorm + lrelu epilogue for geo --------------------
__global__ void k_gn(const float* __restrict__ gw, const float* __restrict__ gb,
                     float* __restrict__ outg) {
    int i = blockIdx.x, h = threadIdx.x;
    __shared__ float sy[HN], sm[32], sv[32];
    float s = g_gy[i*HN + h];
    sy[h] = s;
    __syncthreads();
    if (h < 32) {
        float m = 0.f, v = 0.f;
        #pragma unroll
        for (int q = 0; q < 8; q++) { float y = sy[h*8+q]; m += y; v += y*y; }
        m *= 0.125f; v = v*0.125f - m*m;
        sm[h] = m; sv[h] = rsqrtf(v + 1e-5f);
    }
    __syncthreads();
    float xn = (s - sm[h>>3]) * sv[h>>3] * gw[h] + gb[h];
    outg[i*HN + h] = lrelu(xn);
}

// ---------------- 4. small heads: one warp per output, grid (C, 9) --------
__global__ void k_heads(const float* __restrict__ We,  const float* __restrict__ be,
                        const float* __restrict__ Ws,  const float* __restrict__ bs,
                        const float* __restrict__ Wsi, const float* __restrict__ bsi,
                        float* __restrict__ o_sem, float* __restrict__ o_semins,
                        float* __restrict__ o_exists) {
    int i = blockIdx.x;
    int lane = threadIdx.x & 31, warp = threadIdx.x >> 5;
    int o = blockIdx.y * 8 + warp;
    if (o > SN + PN) return;
    const float* w; float bias;
    if (o < SN)           { w = Ws  + o*HN;       bias = bs[o]; }
    else if (o < SN + PN) { w = Wsi + (o-SN)*HN;  bias = bsi[o-SN]; }
    else                  { w = We;               bias = be[0]; }
    float4 x0 = *(const float4*)&g_cf[i*HN + lane*4];
    float4 x1 = *(const float4*)&g_cf[i*HN + 128 + lane*4];
    float4 w0 = *(const float4*)&w[lane*4];
    float4 w1 = *(const float4*)&w[128 + lane*4];
    float s = w0.x*x0.x + w0.y*x0.y + w0.z*x0.z + w0.w*x0.w
            + w1.x*x1.x + w1.y*x1.y + w1.z*x1.z + w1.w*x1.w;
    #pragma unroll
    for (int q = 16; q; q >>= 1) s += __shfl_xor_sync(0xffffffffu, s, q);
    if (lane == 0) {
        s += bias;
        if (o < SN)           o_sem[i*SN + o] = s;
        else if (o < SN + PN) o_semins[i*PN + (o-SN)] = s;
        else { o_exists[i] = s; g_ok[i] = (s > 0.f) ? 1 : 0; }
    }
}

// ---------------- 5. el materialization + edge_logits ---------------------
__global__ void k_el(const float* __restrict__ Wee, const float* __restrict__ bee,
                     float* __restrict__ o_logits) {
    int j = blockIdx.x, i = blockIdx.y, h = threadIdx.x;
    float e = lrelu(g_AB[i*512 + h] + g_AB[j*512 + 256 + h]);
    int m = i*CN + j;
    g_el[(size_t)m*HN + h] = e;
    float p0 = e*Wee[h], p1 = e*Wee[HN+h], p2 = e*Wee[2*HN+h], p3 = e*Wee[3*HN+h];
    #pragma unroll
    for (int o = 16; o; o >>= 1) {
        p0 += __shfl_down_sync(0xffffffffu, p0, o);
        p1 += __shfl_down_sync(0xffffffffu, p1, o);
        p2 += __shfl_down_sync(0xffffffffu, p2, o);
        p3 += __shfl_down_sync(0xffffffffu, p3, o);
    }
    __shared__ float red[8][4];
    int warp = h >> 5, lane = h & 31;
    if (lane == 0) { red[warp][0]=p0; red[warp][1]=p1; red[warp][2]=p2; red[warp][3]=p3; }
    __syncthreads();
    if (h < 4) {
        float s = bee[h];
        #pragma unroll
        for (int w = 0; w < 8; w++) s += red[w][h];
        o_logits[m*4 + h] = s;
    }
}

// ---------------- 6. E = el(16384x256) @ W3^T(256x512), skip !ok_i --------
__global__ void __launch_bounds__(256, 2) k_gemm(const float* __restrict__ Wne) {
    int bm = blockIdx.x, bn = blockIdx.y;
    if (g_ok[bm] == 0) return;                 // row block = node i; dead if !exists
    __shared__ float As[BK*128];   // [k][m]
    __shared__ float Bs[BK*128];   // [k][n]
    int tid = threadIdx.x;
    int tx = tid & 15, ty = tid >> 4;
    const float* Ag = g_el + (size_t)bm*128*HN;

    float4 va[2], vb[2];
    int lm[2], lc[2];
    #pragma unroll
    for (int q = 0; q < 2; q++) { int l = tid + 256*q; lm[q] = l >> 2; lc[q] = (l & 3)*4; }

    auto ld = [&](int kb) {
        #pragma unroll
        for (int q = 0; q < 2; q++) {
            va[q] = *(const float4*)&Ag[(size_t)lm[q]*HN + kb + lc[q]];
            int ng = bn*128 + lm[q];
            vb[q] = *(const float4*)&Wne[(size_t)ng*772 + 512 + kb + lc[q]];
        }
    };

    float2 c[8][4];
    #pragma unroll
    for (int a = 0; a < 8; a++)
        #pragma unroll
        for (int q = 0; q < 4; q++) c[a][q] = make_float2(0.f, 0.f);

    ld(0);
    for (int kb = 0; kb < HN; kb += BK) {
        #pragma unroll
        for (int q = 0; q < 2; q++) {
            As[(lc[q]+0)*128 + lm[q]] = va[q].x;
            As[(lc[q]+1)*128 + lm[q]] = va[q].y;
            As[(lc[q]+2)*128 + lm[q]] = va[q].z;
            As[(lc[q]+3)*128 + lm[q]] = va[q].w;
            Bs[(lc[q]+0)*128 + lm[q]] = vb[q].x;
            Bs[(lc[q]+1)*128 + lm[q]] = vb[q].y;
            Bs[(lc[q]+2)*128 + lm[q]] = vb[q].z;
            Bs[(lc[q]+3)*128 + lm[q]] = vb[q].w;
        }
        __syncthreads();
        if (kb + BK < HN) ld(kb + BK);     // LDGs overlap compute below
        #pragma unroll
        for (int k = 0; k < BK; k++) {
            float2 b[4], a[4];
            #pragma unroll
            for (int q = 0; q < 4; q++)  b[q]  = *(const float2*)&Bs[k*128 + tx*2 + q*32];
            #pragma unroll
            for (int mi = 0; mi < 4; mi++) a[mi] = *(const float2*)&As[k*128 + ty*2 + mi*32];
            #pragma unroll
            for (int mi = 0; mi < 4; mi++) {
                float2 ax = make_float2(a[mi].x, a[mi].x);
                float2 ay = make_float2(a[mi].y, a[mi].y);
                #pragma unroll
                for (int q = 0; q < 4; q++) {
                    c[mi*2+0][q] = fma2(ax, b[q], c[mi*2+0][q]);
                    c[mi*2+1][q] = fma2(ay, b[q], c[mi*2+1][q]);
                }
            }
        }
        __syncthreads();
    }
    #pragma unroll
    for (int mi = 0; mi < 4; mi++) {
        #pragma unroll
        for (int r = 0; r < 2; r++) {
            int m = bm*128 + ty*2 + mi*32 + r;
            float* Erow = g_E + (size_t)m*512 + bn*128;
            #pragma unroll
            for (int q = 0; q < 4; q++)
                *(float2*)&Erow[tx*2 + q*32] = c[mi*2+r][q];
        }
    }
}

// ---------------- 7. masked max-reduction over (j,t) ----------------------
__global__ void k_reduce(const float* __restrict__ o_logits,
                         const float* __restrict__ Wne, int it) {
    int i = blockIdx.x, h = threadIdx.x;
    float* xout = (it == 0) ? g_x1 : g_x2;
    __shared__ float slog[CN*TN];
    __shared__ int sok[CN];
    #pragma unroll
    for (int l = h; l < CN*TN; l += 256) slog[l] = o_logits[i*CN*TN + l];
    if (h < CN) sok[h] = g_ok[h];
    __syncthreads();
    if (!g_ok[i]) { xout[i*HN + h] = 0.f; return; }
    const float* wr = Wne + ((size_t)it*HN + h)*772 + 768;
    float w40 = wr[0], w41 = wr[1], w42 = wr[2], w43 = wr[3];
    float uh = g_UV[i*512 + h];
    const float* Ep = g_E + (size_t)i*CN*512 + it*HN + h;
    float acc = -__int_as_float(0x7f800000);  // -inf
    #pragma unroll 4
    for (int j = 0; j < CN; j++) {
        if (!sok[j]) continue;
        float l0 = slog[j*4+0], l1 = slog[j*4+1], l2 = slog[j*4+2], l3 = slog[j*4+3];
        bool any = false; float best = -3.4e38f;
        if (l0 > 0.f) { best = l0*w40; any = true; }
        if (l1 > 0.f) { float z = l1*w41; best = any ? fmaxf(best, z) : z; any = true; }
        if (l2 > 0.f) { float z = l2*w42; best = any ? fmaxf(best, z) : z; any = true; }
        if (l3 > 0.f) { float z = l3*w43; best = any ? fmaxf(best, z) : z; any = true; }
        if (!any) continue;
        float z = uh + g_UV[j*512 + 256 + h] + Ep[(size_t)j*512] + best;
        acc = fmaxf(acc, z);
    }
    xout[i*HN + h] = fmaxf(acc, 0.f);
}

// ---------------- launch ---------------------------------------------------
extern "C" void kernel_launch(void* const* d_in, const int* in_sizes, int n_in,
                              void* d_out, int out_size) {
    const float* psf = (const float*)d_in[0];
    const float* pgf = (const float*)d_in[1];
    const float* Wp  = (const float*)d_in[2];
    const float* bp  = (const float*)d_in[3];
    const float* We  = (const float*)d_in[4];
    const float* be  = (const float*)d_in[5];
    const float* Ws  = (const float*)d_in[6];
    const float* bs  = (const float*)d_in[7];
    const float* Wsi = (const float*)d_in[8];
    const float* bsi = (const float*)d_in[9];
    const float* Wel = (const float*)d_in[10];
    const float* bel = (const float*)d_in[11];
    const float* Wee = (const float*)d_in[12];
    const float* bee = (const float*)d_in[13];
    const float* Wne = (const float*)d_in[14];
    const float* bne = (const float*)d_in[15];
    const float* Wc  = (const float*)d_in[16];
    const float* bc  = (const float*)d_in[17];
    const float* Wc2 = (const float*)d_in[18];
    const float* bc2 = (const float*)d_in[19];
    const float* Wgc = (const float*)d_in[20];
    const float* bgc = (const float*)d_in[21];
    const float* Wgp = (const float*)d_in[22];
    const float* bgp = (const float*)d_in[23];
    const float* gw  = (const float*)d_in[24];
    const float* gb  = (const float*)d_in[25];

    float* out       = (float*)d_out;
    float* o_child   = out;                    // 32768
    float* o_geo     = out + 32768;            // 32768
    float* o_sem     = out + 65536;            // 7296
    float* o_semins  = out + 72832;            // 1280
    float* o_exists  = out + 74112;            // 128
    float* o_logits  = out + 74240;            // 65536

    k_gemv_big<<<1024, 256>>>(psf, Wp, bp, pgf, Wgp, bgp);
    k_heads<<<dim3(CN, 9), 256>>>(We, be, Ws, bs, Wsi, bsi, o_sem, o_semins, o_exists);
    k_sgemm<0><<<dim3(16, 4), 256>>>(Wel, bel, nullptr, 0);      // A|B
    k_el<<<dim3(CN, CN), 256>>>(Wee, bee, o_logits);
    k_gemm<<<dim3(128, 4), 256>>>(Wne);                          // E (skips !ok rows)
    k_sgemm<1><<<dim3(8, 4), 256>>>(Wgc, bgc, nullptr, 0);       // geo GEMM
    k_gn<<<CN, 256>>>(gw, gb, o_geo);
    k_sgemm<2><<<dim3(16, 4), 256>>>(Wne, bne, nullptr, 0);      // U|V it=0
    k_reduce<<<CN, 256>>>(o_logits, Wne, 0);
    k_sgemm<2><<<dim3(16, 4), 256>>>(Wne, bne, nullptr, 1);      // U|V it=1
    k_reduce<<<CN, 256>>>(o_logits, Wne, 1);
    k_sgemm<3><<<dim3(8, 4), 256>>>(Wc, bc, nullptr, 0);         // head1
    k_sgemm<4><<<dim3(8, 4), 256>>>(Wc2, bc2, o_child, 0);       // head2
}

// round 4
// speedup vs baseline: 2.0755x; 1.0793x over previous
#include <cuda_runtime.h>

#define CN 128
#define HN 256
#define TN 4
#define SN 57
#define PN 10
#define BK 16
#define ST 130   // padded smem stride for k_gemm tiles

// ---------------- scratch (device globals; no allocation) ----------------
__device__ float g_cf[CN*HN];          // cf (C,H)
__device__ float g_pg[CN*HN];          // pg (C,H)
__device__ float g_AB[CN*2*HN];        // [A | B+bel]  (C,512)
__device__ float g_gy[CN*HN];          // geo pre-GN
__device__ float g_E [CN*CN*2*HN];     // E (C*C, 512) 33.5MB
__device__ float g_UV[CN*2*HN];        // [U+bne | V] (C,512)
__device__ float g_ch[CN*HN];
__device__ float g_x1[CN*HN];
__device__ float g_x2[CN*HN];
__device__ int   g_ok[CN];

__device__ __forceinline__ float lrelu(float x){ return x > 0.f ? x : 0.01f*x; }

__device__ __forceinline__ float2 fma2(float2 a, float2 b, float2 c) {
    unsigned long long au = *reinterpret_cast<unsigned long long*>(&a);
    unsigned long long bu = *reinterpret_cast<unsigned long long*>(&b);
    unsigned long long cu = *reinterpret_cast<unsigned long long*>(&c);
    unsigned long long du;
    asm("fma.rn.f32x2 %0, %1, %2, %3;" : "=l"(du) : "l"(au), "l"(bu), "l"(cu));
    return *reinterpret_cast<float2*>(&du);
}

// ---------------- 1. big GEMVs: cf and pg (32768 outs each, K=256) --------
__global__ void k_gemv_big(const float* __restrict__ psf, const float* __restrict__ Wp,
                           const float* __restrict__ bp,  const float* __restrict__ pgf,
                           const float* __restrict__ Wgp, const float* __restrict__ bgp) {
    __shared__ float sin_[HN];
    bool second = blockIdx.x >= 512;
    const float* in = second ? pgf : psf;
    const float* W  = second ? Wgp : Wp;
    const float* b  = second ? bgp : bp;
    float* out      = second ? g_pg : g_cf;
    int base = (blockIdx.x & 511) * 64;
    sin_[threadIdx.x] = in[threadIdx.x];
    __syncthreads();
    int warp = threadIdx.x >> 5, lane = threadIdx.x & 31;
    #pragma unroll
    for (int rr = 0; rr < 8; rr++) {
        int r = base + warp*8 + rr;
        const float* wr = W + (size_t)r * HN;
        float s = 0.f;
        #pragma unroll
        for (int q = 0; q < 2; q++) {
            float4 wv = *(const float4*)&wr[lane*4 + 128*q];
            float4 xv = *(const float4*)&sin_[lane*4 + 128*q];
            s += wv.x*xv.x + wv.y*xv.y + wv.z*xv.z + wv.w*xv.w;
        }
        #pragma unroll
        for (int o = 16; o; o >>= 1) s += __shfl_down_sync(0xffffffffu, s, o);
        if (lane == 0) out[r] = lrelu(s + b[r]);
    }
}

// ---------------- 2. generic tiled 32x32x32 SGEMM, M=128, double-buffered --
template<int MODE>
__global__ void __launch_bounds__(256) k_sgemm(const float* __restrict__ W,
                                               const float* __restrict__ b1,
                                               float* __restrict__ out, int it) {
    constexpr int K  = (MODE == 3) ? 768 : 256;
    constexpr int NT = K / 32;
    __shared__ float Xs[2][32][33];
    __shared__ float Ws[2][32][33];
    int tid = threadIdx.x;
    int bn = blockIdx.x, bm = blockIdx.y;
    int r  = tid >> 3, c4 = (tid & 7) * 4;
    int tx = tid & 15, ty = tid >> 4;
    int m0 = bm*32 + r;
    int n0 = bn*32 + r;

    const float* wrow;
    if      (MODE == 0) wrow = W + (n0 < 256 ? (size_t)n0*512 : (size_t)(n0-256)*512 + 256);
    else if (MODE == 1) wrow = W + (size_t)n0*256;
    else if (MODE == 2) wrow = W + ((size_t)it*256 + (n0 & 255))*772 + (n0 >= 256 ? 256 : 0);
    else if (MODE == 3) wrow = W + (size_t)n0*768;
    else                wrow = W + (size_t)n0*256;

    const float* Xbase;
    if      (MODE == 0) Xbase = g_cf;
    else if (MODE == 1) Xbase = g_pg;
    else if (MODE == 2) Xbase = it ? g_x1 : g_cf;
    else if (MODE == 4) Xbase = g_ch;
    else                Xbase = g_cf;

    auto loadX = [&](int kb) -> float4 {
        if (MODE == 3) {
            int g = kb + c4;
            const float* src = (g < 256) ? g_cf : (g < 512 ? g_x1 : g_x2);
            return *(const float4*)(src + (size_t)m0*256 + (g & 255));
        }
        return *(const float4*)(Xbase + (size_t)m0*256 + kb + c4);
    };

    float4 xv = loadX(0);
    float4 wv = *(const float4*)(wrow + c4);
    float a00 = 0.f, a01 = 0.f, a10 = 0.f, a11 = 0.f;

    for (int t = 0; t < NT; t++) {
        int cur = t & 1;
        Xs[cur][c4+0][r] = xv.x; Xs[cur][c4+1][r] = xv.y;
        Xs[cur][c4+2][r] = xv.z; Xs[cur][c4+3][r] = xv.w;
        Ws[cur][c4+0][r] = wv.x; Ws[cur][c4+1][r] = wv.y;
        Ws[cur][c4+2][r] = wv.z; Ws[cur][c4+3][r] = wv.w;
        __syncthreads();
        if (t + 1 < NT) {
            xv = loadX((t+1)*32);
            wv = *(const float4*)(wrow + (t+1)*32 + c4);
        }
        #pragma unroll
        for (int k = 0; k < 32; k++) {
            float ax = Xs[cur][k][ty*2], ay = Xs[cur][k][ty*2+1];
            float bx = Ws[cur][k][tx*2], by = Ws[cur][k][tx*2+1];
            a00 += ax*bx; a01 += ax*by;
            a10 += ay*bx; a11 += ay*by;
        }
    }

    int m = bm*32 + ty*2, n = bn*32 + tx*2;
    float accs[2][2] = {{a00, a01}, {a10, a11}};
    #pragma unroll
    for (int mi = 0; mi < 2; mi++) {
        #pragma unroll
        for (int ni = 0; ni < 2; ni++) {
            int mm = m + mi, nn = n + ni;
            float v = accs[mi][ni];
            if      (MODE == 0) g_AB[mm*512 + nn] = (nn >= 256) ? v + b1[nn-256] : v;
            else if (MODE == 1) g_gy[mm*256 + nn] = v + b1[nn];
            else if (MODE == 2) g_UV[mm*512 + nn] = (nn < 256) ? v + b1[it*256 + nn] : v;
            else if (MODE == 3) g_ch[mm*256 + nn] = lrelu(v + b1[nn]);
            else                out [mm*256 + nn] = lrelu(v + b1[nn]);
        }
    }
}

// ---------------- 3. groupnorm + lrelu epilogue for geo --------------------
__global__ void k_gn(const float* __restrict__ gw, const float* __restrict__ gb,
                     float* __restrict__ outg) {
    int i = blockIdx.x, h = threadIdx.x;
    __shared__ float sy[HN], sm[32], sv[32];
    float s = g_gy[i*HN + h];
    sy[h] = s;
    __syncthreads();
    if (h < 32) {
        float m = 0.f, v = 0.f;
        #pragma unroll
        for (int q = 0; q < 8; q++) { float y = sy[h*8+q]; m += y; v += y*y; }
        m *= 0.125f; v = v*0.125f - m*m;
        sm[h] = m; sv[h] = rsqrtf(v + 1e-5f);
    }
    __syncthreads();
    float xn = (s - sm[h>>3]) * sv[h>>3] * gw[h] + gb[h];
    outg[i*HN + h] = lrelu(xn);
}

// ---------------- 4. small heads: one warp per output, grid (C, 9) --------
__global__ void k_heads(const float* __restrict__ We,  const float* __restrict__ be,
                        const float* __restrict__ Ws,  const float* __restrict__ bs,
                        const float* __restrict__ Wsi, const float* __restrict__ bsi,
                        float* __restrict__ o_sem, float* __restrict__ o_semins,
                        float* __restrict__ o_exists) {
    int i = blockIdx.x;
    int lane = threadIdx.x & 31, warp = threadIdx.x >> 5;
    int o = blockIdx.y * 8 + warp;
    if (o > SN + PN) return;
    const float* w; float bias;
    if (o < SN)           { w = Ws  + o*HN;       bias = bs[o]; }
    else if (o < SN + PN) { w = Wsi + (o-SN)*HN;  bias = bsi[o-SN]; }
    else                  { w = We;               bias = be[0]; }
    float4 x0 = *(const float4*)&g_cf[i*HN + lane*4];
    float4 x1 = *(const float4*)&g_cf[i*HN + 128 + lane*4];
    float4 w0 = *(const float4*)&w[lane*4];
    float4 w1 = *(const float4*)&w[128 + lane*4];
    float s = w0.x*x0.x + w0.y*x0.y + w0.z*x0.z + w0.w*x0.w
            + w1.x*x1.x + w1.y*x1.y + w1.z*x1.z + w1.w*x1.w;
    #pragma unroll
    for (int q = 16; q; q >>= 1) s += __shfl_xor_sync(0xffffffffu, s, q);
    if (lane == 0) {
        s += bias;
        if (o < SN)           o_sem[i*SN + o] = s;
        else if (o < SN + PN) o_semins[i*PN + (o-SN)] = s;
        else { o_exists[i] = s; g_ok[i] = (s > 0.f) ? 1 : 0; }
    }
}

// ---------------- 5. E = el @ W3^T with el computed on the fly ------------
// el[(bm,j),h] = lrelu(A[bm,h] + B[j,h]);  A|B in g_AB.  Skips !ok rows.
__global__ void __launch_bounds__(256, 2) k_gemm(const float* __restrict__ Wne) {
    int bm = blockIdx.x, bn = blockIdx.y;
    if (g_ok[bm] == 0) return;
    __shared__ float As[BK*ST];   // [k][j]
    __shared__ float Bs[BK*ST];   // [k][n]
    int tid = threadIdx.x;
    int tx = tid & 15, ty = tid >> 4;

    float4 va[2], vb[2];
    int lm[2], lc[2];
    #pragma unroll
    for (int q = 0; q < 2; q++) { int l = tid + 256*q; lm[q] = l >> 2; lc[q] = (l & 3)*4; }

    auto ld = [&](int kb) {
        #pragma unroll
        for (int q = 0; q < 2; q++) {
            float4 a = *(const float4*)&g_AB[bm*512 + kb + lc[q]];
            float4 b = *(const float4*)&g_AB[lm[q]*512 + 256 + kb + lc[q]];
            va[q].x = lrelu(a.x + b.x);
            va[q].y = lrelu(a.y + b.y);
            va[q].z = lrelu(a.z + b.z);
            va[q].w = lrelu(a.w + b.w);
            int ng = bn*128 + lm[q];
            vb[q] = *(const float4*)&Wne[(size_t)ng*772 + 512 + kb + lc[q]];
        }
    };

    float2 c[8][4];
    #pragma unroll
    for (int a = 0; a < 8; a++)
        #pragma unroll
        for (int q = 0; q < 4; q++) c[a][q] = make_float2(0.f, 0.f);

    ld(0);
    for (int kb = 0; kb < HN; kb += BK) {
        #pragma unroll
        for (int q = 0; q < 2; q++) {
            As[(lc[q]+0)*ST + lm[q]] = va[q].x;
            As[(lc[q]+1)*ST + lm[q]] = va[q].y;
            As[(lc[q]+2)*ST + lm[q]] = va[q].z;
            As[(lc[q]+3)*ST + lm[q]] = va[q].w;
            Bs[(lc[q]+0)*ST + lm[q]] = vb[q].x;
            Bs[(lc[q]+1)*ST + lm[q]] = vb[q].y;
            Bs[(lc[q]+2)*ST + lm[q]] = vb[q].z;
            Bs[(lc[q]+3)*ST + lm[q]] = vb[q].w;
        }
        __syncthreads();
        if (kb + BK < HN) ld(kb + BK);
        #pragma unroll
        for (int k = 0; k < BK; k++) {
            float2 b[4], a[4];
            #pragma unroll
            for (int q = 0; q < 4; q++)  b[q]  = *(const float2*)&Bs[k*ST + tx*2 + q*32];
            #pragma unroll
            for (int mi = 0; mi < 4; mi++) a[mi] = *(const float2*)&As[k*ST + ty*2 + mi*32];
            #pragma unroll
            for (int mi = 0; mi < 4; mi++) {
                float2 ax = make_float2(a[mi].x, a[mi].x);
                float2 ay = make_float2(a[mi].y, a[mi].y);
                #pragma unroll
                for (int q = 0; q < 4; q++) {
                    c[mi*2+0][q] = fma2(ax, b[q], c[mi*2+0][q]);
                    c[mi*2+1][q] = fma2(ay, b[q], c[mi*2+1][q]);
                }
            }
        }
        __syncthreads();
    }
    #pragma unroll
    for (int mi = 0; mi < 4; mi++) {
        #pragma unroll
        for (int r = 0; r < 2; r++) {
            int m = bm*128 + ty*2 + mi*32 + r;
            float* Erow = g_E + (size_t)m*512 + bn*128;
            #pragma unroll
            for (int q = 0; q < 4; q++)
                *(float2*)&Erow[tx*2 + q*32] = c[mi*2+r][q];
        }
    }
}

// ---------------- 6. edge logits only (el recomputed on the fly) ----------
__global__ void __launch_bounds__(256) k_el(const float* __restrict__ Wee,
                                            const float* __restrict__ bee,
                                            float* __restrict__ o_logits) {
    int i = blockIdx.x;
    int t = threadIdx.x;
    int j = t & 127, half = t >> 7;
    __shared__ float sA[256];
    __shared__ float sW[4*256];
    __shared__ float sB[128*33];
    __shared__ float sP[128*8];
    sA[t] = g_AB[i*512 + t];
    #pragma unroll
    for (int l = t; l < 1024; l += 256) sW[l] = Wee[l];
    float acc0 = 0.f, acc1 = 0.f, acc2 = 0.f, acc3 = 0.f;
    for (int c0 = 0; c0 < 256; c0 += 32) {
        __syncthreads();
        #pragma unroll
        for (int idx = t; idx < 1024; idx += 256) {
            int jj = idx >> 3, f4 = (idx & 7) * 4;
            float4 v = *(const float4*)&g_AB[jj*512 + 256 + c0 + f4];
            sB[jj*33 + f4+0] = v.x; sB[jj*33 + f4+1] = v.y;
            sB[jj*33 + f4+2] = v.z; sB[jj*33 + f4+3] = v.w;
        }
        __syncthreads();
        int h0 = half*16;
        #pragma unroll
        for (int hh = 0; hh < 16; hh++) {
            int h = h0 + hh;
            float e = lrelu(sA[c0+h] + sB[j*33 + h]);
            acc0 += e * sW[        c0+h];
            acc1 += e * sW[256  + c0+h];
            acc2 += e * sW[512  + c0+h];
            acc3 += e * sW[768  + c0+h];
        }
    }
    sP[(j*2+half)*4 + 0] = acc0;
    sP[(j*2+half)*4 + 1] = acc1;
    sP[(j*2+half)*4 + 2] = acc2;
    sP[(j*2+half)*4 + 3] = acc3;
    __syncthreads();
    if (t < 128) {
        float4 o;
        o.x = sP[t*8+0] + sP[t*8+4] + bee[0];
        o.y = sP[t*8+1] + sP[t*8+5] + bee[1];
        o.z = sP[t*8+2] + sP[t*8+6] + bee[2];
        o.w = sP[t*8+3] + sP[t*8+7] + bee[3];
        *(float4*)&o_logits[(i*128 + t)*4] = o;
    }
}

// ---------------- 7. masked max-reduction over (j,t) ----------------------
__global__ void k_reduce(const float* __restrict__ o_logits,
                         const float* __restrict__ Wne, int it) {
    int i = blockIdx.x, h = threadIdx.x;
    float* xout = (it == 0) ? g_x1 : g_x2;
    __shared__ float slog[CN*TN];
    __shared__ int sok[CN];
    #pragma unroll
    for (int l = h; l < CN*TN; l += 256) slog[l] = o_logits[i*CN*TN + l];
    if (h < CN) sok[h] = g_ok[h];
    __syncthreads();
    if (!g_ok[i]) { xout[i*HN + h] = 0.f; return; }
    const float* wr = Wne + ((size_t)it*HN + h)*772 + 768;
    float w40 = wr[0], w41 = wr[1], w42 = wr[2], w43 = wr[3];
    float uh = g_UV[i*512 + h];
    const float* Ep = g_E + (size_t)i*CN*512 + it*HN + h;
    float acc = -__int_as_float(0x7f800000);  // -inf
    #pragma unroll 4
    for (int j = 0; j < CN; j++) {
        if (!sok[j]) continue;
        float l0 = slog[j*4+0], l1 = slog[j*4+1], l2 = slog[j*4+2], l3 = slog[j*4+3];
        bool any = false; float best = -3.4e38f;
        if (l0 > 0.f) { best = l0*w40; any = true; }
        if (l1 > 0.f) { float z = l1*w41; best = any ? fmaxf(best, z) : z; any = true; }
        if (l2 > 0.f) { float z = l2*w42; best = any ? fmaxf(best, z) : z; any = true; }
        if (l3 > 0.f) { float z = l3*w43; best = any ? fmaxf(best, z) : z; any = true; }
        if (!any) continue;
        float z = uh + g_UV[j*512 + 256 + h] + Ep[(size_t)j*512] + best;
        acc = fmaxf(acc, z);
    }
    xout[i*HN + h] = fmaxf(acc, 0.f);
}

// ---------------- launch ---------------------------------------------------
extern "C" void kernel_launch(void* const* d_in, const int* in_sizes, int n_in,
                              void* d_out, int out_size) {
    const float* psf = (const float*)d_in[0];
    const float* pgf = (const float*)d_in[1];
    const float* Wp  = (const float*)d_in[2];
    const float* bp  = (const float*)d_in[3];
    const float* We  = (const float*)d_in[4];
    const float* be  = (const float*)d_in[5];
    const float* Ws  = (const float*)d_in[6];
    const float* bs  = (const float*)d_in[7];
    const float* Wsi = (const float*)d_in[8];
    const float* bsi = (const float*)d_in[9];
    const float* Wel = (const float*)d_in[10];
    const float* bel = (const float*)d_in[11];
    const float* Wee = (const float*)d_in[12];
    const float* bee = (const float*)d_in[13];
    const float* Wne = (const float*)d_in[14];
    const float* bne = (const float*)d_in[15];
    const float* Wc  = (const float*)d_in[16];
    const float* bc  = (const float*)d_in[17];
    const float* Wc2 = (const float*)d_in[18];
    const float* bc2 = (const float*)d_in[19];
    const float* Wgc = (const float*)d_in[20];
    const float* bgc = (const float*)d_in[21];
    const float* Wgp = (const float*)d_in[22];
    const float* bgp = (const float*)d_in[23];
    const float* gw  = (const float*)d_in[24];
    const float* gb  = (const float*)d_in[25];

    float* out       = (float*)d_out;
    float* o_child   = out;                    // 32768
    float* o_geo     = out + 32768;            // 32768
    float* o_sem     = out + 65536;            // 7296
    float* o_semins  = out + 72832;            // 1280
    float* o_exists  = out + 74112;            // 128
    float* o_logits  = out + 74240;            // 65536

    k_gemv_big<<<1024, 256>>>(psf, Wp, bp, pgf, Wgp, bgp);          // 1
    k_heads<<<dim3(CN, 9), 256>>>(We, be, Ws, bs, Wsi, bsi,
                                  o_sem, o_semins, o_exists);       // 2
    k_sgemm<0><<<dim3(16, 4), 256>>>(Wel, bel, nullptr, 0);         // 3  A|B
    k_gemm<<<dim3(128, 4), 256>>>(Wne);                             // 4  E  (profiled)
    k_el<<<CN, 256>>>(Wee, bee, o_logits);                          // 5  logits
    k_sgemm<1><<<dim3(8, 4), 256>>>(Wgc, bgc, nullptr, 0);          // 6  geo GEMM
    k_gn<<<CN, 256>>>(gw, gb, o_geo);                               // 7
    k_sgemm<2><<<dim3(16, 4), 256>>>(Wne, bne, nullptr, 0);         // 8  U|V it=0
    k_reduce<<<CN, 256>>>(o_logits, Wne, 0);                        // 9
    k_sgemm<2><<<dim3(16, 4), 256>>>(Wne, bne, nullptr, 1);         // 10 U|V it=1
    k_reduce<<<CN, 256>>>(o_logits, Wne, 1);                        // 11
    k_sgemm<3><<<dim3(8, 4), 256>>>(Wc, bc, nullptr, 0);            // 12 head1
    k_sgemm<4><<<dim3(8, 4), 256>>>(Wc2, bc2, o_child, 0);          // 13 head2
}

// round 5
// speedup vs baseline: 2.3985x; 1.1556x over previous
#include <cuda_runtime.h>

#define CN 128
#define HN 256
#define TN 4
#define SN 57
#define PN 10
#define BK 16
#define ST 130   // padded smem stride for k_gemm tiles

// ---------------- scratch (device globals; no allocation) ----------------
__device__ float g_cf[CN*HN];          // cf (C,H)
__device__ float g_pg[CN*HN];          // pg (C,H)
__device__ float g_AB[CN*2*HN];        // [A | B+bel]  (C,512)
__device__ float g_gy[CN*HN];          // geo pre-GN
__device__ float g_E [CN*CN*2*HN];     // E (C*C, 512) 33.5MB
__device__ float g_UV[CN*2*HN];        // [U+bne | V] (C,512)
__device__ float g_ch[CN*HN];
__device__ float g_x1[CN*HN];
__device__ float g_x2[CN*HN];
__device__ int   g_ok[CN];

__device__ __forceinline__ float lrelu(float x){ return x > 0.f ? x : 0.01f*x; }

__device__ __forceinline__ float2 fma2(float2 a, float2 b, float2 c) {
    unsigned long long au = *reinterpret_cast<unsigned long long*>(&a);
    unsigned long long bu = *reinterpret_cast<unsigned long long*>(&b);
    unsigned long long cu = *reinterpret_cast<unsigned long long*>(&c);
    unsigned long long du;
    asm("fma.rn.f32x2 %0, %1, %2, %3;" : "=l"(du) : "l"(au), "l"(bu), "l"(cu));
    return *reinterpret_cast<float2*>(&du);
}

// ---------------- 1. big GEMVs: cf and pg (32768 outs each, K=256) --------
__global__ void k_gemv_big(const float* __restrict__ psf, const float* __restrict__ Wp,
                           const float* __restrict__ bp,  const float* __restrict__ pgf,
                           const float* __restrict__ Wgp, const float* __restrict__ bgp) {
    __shared__ float sin_[HN];
    bool second = blockIdx.x >= 512;
    const float* in = second ? pgf : psf;
    const float* W  = second ? Wgp : Wp;
    const float* b  = second ? bgp : bp;
    float* out      = second ? g_pg : g_cf;
    int base = (blockIdx.x & 511) * 64;
    sin_[threadIdx.x] = in[threadIdx.x];
    __syncthreads();
    int warp = threadIdx.x >> 5, lane = threadIdx.x & 31;
    #pragma unroll
    for (int rr = 0; rr < 8; rr++) {
        int r = base + warp*8 + rr;
        const float* wr = W + (size_t)r * HN;
        float s = 0.f;
        #pragma unroll
        for (int q = 0; q < 2; q++) {
            float4 wv = *(const float4*)&wr[lane*4 + 128*q];
            float4 xv = *(const float4*)&sin_[lane*4 + 128*q];
            s += wv.x*xv.x + wv.y*xv.y + wv.z*xv.z + wv.w*xv.w;
        }
        #pragma unroll
        for (int o = 16; o; o >>= 1) s += __shfl_down_sync(0xffffffffu, s, o);
        if (lane == 0) out[r] = lrelu(s + b[r]);
    }
}

// ---------------- 2. generic tiled 32x32x32 SGEMM, M=128, double-buffered --
template<int MODE>
__global__ void __launch_bounds__(256) k_sgemm(const float* __restrict__ W,
                                               const float* __restrict__ b1,
                                               float* __restrict__ out, int it) {
    constexpr int K  = (MODE == 3) ? 768 : 256;
    constexpr int NT = K / 32;
    __shared__ float Xs[2][32][33];
    __shared__ float Ws[2][32][33];
    int tid = threadIdx.x;
    int bn = blockIdx.x, bm = blockIdx.y;
    int r  = tid >> 3, c4 = (tid & 7) * 4;
    int tx = tid & 15, ty = tid >> 4;
    int m0 = bm*32 + r;
    int n0 = bn*32 + r;

    const float* wrow;
    if      (MODE == 0) wrow = W + (n0 < 256 ? (size_t)n0*512 : (size_t)(n0-256)*512 + 256);
    else if (MODE == 1) wrow = W + (size_t)n0*256;
    else if (MODE == 2) wrow = W + ((size_t)it*256 + (n0 & 255))*772 + (n0 >= 256 ? 256 : 0);
    else if (MODE == 3) wrow = W + (size_t)n0*768;
    else                wrow = W + (size_t)n0*256;

    const float* Xbase;
    if      (MODE == 0) Xbase = g_cf;
    else if (MODE == 1) Xbase = g_pg;
    else if (MODE == 2) Xbase = it ? g_x1 : g_cf;
    else if (MODE == 4) Xbase = g_ch;
    else                Xbase = g_cf;

    auto loadX = [&](int kb) -> float4 {
        if (MODE == 3) {
            int g = kb + c4;
            const float* src = (g < 256) ? g_cf : (g < 512 ? g_x1 : g_x2);
            return *(const float4*)(src + (size_t)m0*256 + (g & 255));
        }
        return *(const float4*)(Xbase + (size_t)m0*256 + kb + c4);
    };

    float4 xv = loadX(0);
    float4 wv = *(const float4*)(wrow + c4);
    float a00 = 0.f, a01 = 0.f, a10 = 0.f, a11 = 0.f;

    for (int t = 0; t < NT; t++) {
        int cur = t & 1;
        Xs[cur][c4+0][r] = xv.x; Xs[cur][c4+1][r] = xv.y;
        Xs[cur][c4+2][r] = xv.z; Xs[cur][c4+3][r] = xv.w;
        Ws[cur][c4+0][r] = wv.x; Ws[cur][c4+1][r] = wv.y;
        Ws[cur][c4+2][r] = wv.z; Ws[cur][c4+3][r] = wv.w;
        __syncthreads();
        if (t + 1 < NT) {
            xv = loadX((t+1)*32);
            wv = *(const float4*)(wrow + (t+1)*32 + c4);
        }
        #pragma unroll
        for (int k = 0; k < 32; k++) {
            float ax = Xs[cur][k][ty*2], ay = Xs[cur][k][ty*2+1];
            float bx = Ws[cur][k][tx*2], by = Ws[cur][k][tx*2+1];
            a00 += ax*bx; a01 += ax*by;
            a10 += ay*bx; a11 += ay*by;
        }
    }

    int m = bm*32 + ty*2, n = bn*32 + tx*2;
    float accs[2][2] = {{a00, a01}, {a10, a11}};
    #pragma unroll
    for (int mi = 0; mi < 2; mi++) {
        #pragma unroll
        for (int ni = 0; ni < 2; ni++) {
            int mm = m + mi, nn = n + ni;
            float v = accs[mi][ni];
            if      (MODE == 0) g_AB[mm*512 + nn] = (nn >= 256) ? v + b1[nn-256] : v;
            else if (MODE == 1) g_gy[mm*256 + nn] = v + b1[nn];
            else if (MODE == 2) g_UV[mm*512 + nn] = (nn < 256) ? v + b1[it*256 + nn] : v;
            else if (MODE == 3) g_ch[mm*256 + nn] = lrelu(v + b1[nn]);
            else                out [mm*256 + nn] = lrelu(v + b1[nn]);
        }
    }
}

// ---------------- 3. groupnorm + lrelu epilogue for geo --------------------
__global__ void k_gn(const float* __restrict__ gw, const float* __restrict__ gb,
                     float* __restrict__ outg) {
    int i = blockIdx.x, h = threadIdx.x;
    __shared__ float sy[HN], sm[32], sv[32];
    float s = g_gy[i*HN + h];
    sy[h] = s;
    __syncthreads();
    if (h < 32) {
        float m = 0.f, v = 0.f;
        #pragma unroll
        for (int q = 0; q < 8; q++) { float y = sy[h*8+q]; m += y; v += y*y; }
        m *= 0.125f; v = v*0.125f - m*m;
        sm[h] = m; sv[h] = rsqrtf(v + 1e-5f);
    }
    __syncthreads();
    float xn = (s - sm[h>>3]) * sv[h>>3] * gw[h] + gb[h];
    outg[i*HN + h] = lrelu(xn);
}

// ---------------- 4. small heads: one warp per output, grid (C, 9) --------
__global__ void k_heads(const float* __restrict__ We,  const float* __restrict__ be,
                        const float* __restrict__ Ws,  const float* __restrict__ bs,
                        const float* __restrict__ Wsi, const float* __restrict__ bsi,
                        float* __restrict__ o_sem, float* __restrict__ o_semins,
                        float* __restrict__ o_exists) {
    int i = blockIdx.x;
    int lane = threadIdx.x & 31, warp = threadIdx.x >> 5;
    int o = blockIdx.y * 8 + warp;
    if (o > SN + PN) return;
    const float* w; float bias;
    if (o < SN)           { w = Ws  + o*HN;       bias = bs[o]; }
    else if (o < SN + PN) { w = Wsi + (o-SN)*HN;  bias = bsi[o-SN]; }
    else                  { w = We;               bias = be[0]; }
    float4 x0 = *(const float4*)&g_cf[i*HN + lane*4];
    float4 x1 = *(const float4*)&g_cf[i*HN + 128 + lane*4];
    float4 w0 = *(const float4*)&w[lane*4];
    float4 w1 = *(const float4*)&w[128 + lane*4];
    float s = w0.x*x0.x + w0.y*x0.y + w0.z*x0.z + w0.w*x0.w
            + w1.x*x1.x + w1.y*x1.y + w1.z*x1.z + w1.w*x1.w;
    #pragma unroll
    for (int q = 16; q; q >>= 1) s += __shfl_xor_sync(0xffffffffu, s, q);
    if (lane == 0) {
        s += bias;
        if (o < SN)           o_sem[i*SN + o] = s;
        else if (o < SN + PN) o_semins[i*PN + (o-SN)] = s;
        else { o_exists[i] = s; g_ok[i] = (s > 0.f) ? 1 : 0; }
    }
}

// ---------------- 5. E = el @ W3^T, el on the fly, 2-stage double buffer ---
__global__ void __launch_bounds__(256, 2) k_gemm(const float* __restrict__ Wne) {
    int bm = blockIdx.x, bn = blockIdx.y;
    if (g_ok[bm] == 0) return;
    __shared__ float As[2][BK*ST];   // [k][j]
    __shared__ float Bs[2][BK*ST];   // [k][n]
    int tid = threadIdx.x;
    int tx = tid & 15, ty = tid >> 4;

    float4 va[2], vb[2];
    int lm[2], lc[2];
    #pragma unroll
    for (int q = 0; q < 2; q++) { int l = tid + 256*q; lm[q] = l >> 2; lc[q] = (l & 3)*4; }

    auto ld = [&](int kb) {
        #pragma unroll
        for (int q = 0; q < 2; q++) {
            float4 a = *(const float4*)&g_AB[bm*512 + kb + lc[q]];
            float4 b = *(const float4*)&g_AB[lm[q]*512 + 256 + kb + lc[q]];
            va[q].x = lrelu(a.x + b.x);
            va[q].y = lrelu(a.y + b.y);
            va[q].z = lrelu(a.z + b.z);
            va[q].w = lrelu(a.w + b.w);
            int ng = bn*128 + lm[q];
            vb[q] = *(const float4*)&Wne[(size_t)ng*772 + 512 + kb + lc[q]];
        }
    };
    auto sts = [&](int s) {
        #pragma unroll
        for (int q = 0; q < 2; q++) {
            As[s][(lc[q]+0)*ST + lm[q]] = va[q].x;
            As[s][(lc[q]+1)*ST + lm[q]] = va[q].y;
            As[s][(lc[q]+2)*ST + lm[q]] = va[q].z;
            As[s][(lc[q]+3)*ST + lm[q]] = va[q].w;
            Bs[s][(lc[q]+0)*ST + lm[q]] = vb[q].x;
            Bs[s][(lc[q]+1)*ST + lm[q]] = vb[q].y;
            Bs[s][(lc[q]+2)*ST + lm[q]] = vb[q].z;
            Bs[s][(lc[q]+3)*ST + lm[q]] = vb[q].w;
        }
    };

    float2 c[8][4];
    #pragma unroll
    for (int a = 0; a < 8; a++)
        #pragma unroll
        for (int q = 0; q < 4; q++) c[a][q] = make_float2(0.f, 0.f);

    ld(0);
    sts(0);
    constexpr int NT = HN / BK;
    for (int t = 0; t < NT; t++) {
        int cur = t & 1;
        __syncthreads();
        if (t + 1 < NT) ld((t+1)*BK);
        #pragma unroll
        for (int k = 0; k < BK; k++) {
            float2 b[4], a[4];
            #pragma unroll
            for (int q = 0; q < 4; q++)  b[q]  = *(const float2*)&Bs[cur][k*ST + tx*2 + q*32];
            #pragma unroll
            for (int mi = 0; mi < 4; mi++) a[mi] = *(const float2*)&As[cur][k*ST + ty*2 + mi*32];
            #pragma unroll
            for (int mi = 0; mi < 4; mi++) {
                float2 ax = make_float2(a[mi].x, a[mi].x);
                float2 ay = make_float2(a[mi].y, a[mi].y);
                #pragma unroll
                for (int q = 0; q < 4; q++) {
                    c[mi*2+0][q] = fma2(ax, b[q], c[mi*2+0][q]);
                    c[mi*2+1][q] = fma2(ay, b[q], c[mi*2+1][q]);
                }
            }
        }
        if (t + 1 < NT) sts(cur ^ 1);
    }
    #pragma unroll
    for (int mi = 0; mi < 4; mi++) {
        #pragma unroll
        for (int r = 0; r < 2; r++) {
            int m = bm*128 + ty*2 + mi*32 + r;
            float* Erow = g_E + (size_t)m*512 + bn*128;
            #pragma unroll
            for (int q = 0; q < 4; q++)
                *(float2*)&Erow[tx*2 + q*32] = c[mi*2+r][q];
        }
    }
}

// ---------------- 6. edge logits only (el recomputed on the fly) ----------
__global__ void __launch_bounds__(256) k_el(const float* __restrict__ Wee,
                                            const float* __restrict__ bee,
                                            float* __restrict__ o_logits) {
    int i = blockIdx.x;
    int t = threadIdx.x;
    int j = t & 127, half = t >> 7;
    __shared__ float sA[256];
    __shared__ float sW[4*256];
    __shared__ float sB[128*33];
    __shared__ float sP[128*8];
    sA[t] = g_AB[i*512 + t];
    #pragma unroll
    for (int l = t; l < 1024; l += 256) sW[l] = Wee[l];
    float acc0 = 0.f, acc1 = 0.f, acc2 = 0.f, acc3 = 0.f;
    for (int c0 = 0; c0 < 256; c0 += 32) {
        __syncthreads();
        #pragma unroll
        for (int idx = t; idx < 1024; idx += 256) {
            int jj = idx >> 3, f4 = (idx & 7) * 4;
            float4 v = *(const float4*)&g_AB[jj*512 + 256 + c0 + f4];
            sB[jj*33 + f4+0] = v.x; sB[jj*33 + f4+1] = v.y;
            sB[jj*33 + f4+2] = v.z; sB[jj*33 + f4+3] = v.w;
        }
        __syncthreads();
        int h0 = half*16;
        #pragma unroll
        for (int hh = 0; hh < 16; hh++) {
            int h = h0 + hh;
            float e = lrelu(sA[c0+h] + sB[j*33 + h]);
            acc0 += e * sW[        c0+h];
            acc1 += e * sW[256  + c0+h];
            acc2 += e * sW[512  + c0+h];
            acc3 += e * sW[768  + c0+h];
        }
    }
    sP[(j*2+half)*4 + 0] = acc0;
    sP[(j*2+half)*4 + 1] = acc1;
    sP[(j*2+half)*4 + 2] = acc2;
    sP[(j*2+half)*4 + 3] = acc3;
    __syncthreads();
    if (t < 128) {
        float4 o;
        o.x = sP[t*8+0] + sP[t*8+4] + bee[0];
        o.y = sP[t*8+1] + sP[t*8+5] + bee[1];
        o.z = sP[t*8+2] + sP[t*8+6] + bee[2];
        o.w = sP[t*8+3] + sP[t*8+7] + bee[3];
        *(float4*)&o_logits[(i*128 + t)*4] = o;
    }
}

// ---------------- 7. masked max-reduction over (j,t), branchless ----------
__global__ void k_reduce(const float* __restrict__ o_logits,
                         const float* __restrict__ Wne, int it) {
    int i = blockIdx.x, h = threadIdx.x;
    float* xout = (it == 0) ? g_x1 : g_x2;
    __shared__ float slog[CN*TN];
    #pragma unroll
    for (int l = h; l < CN*TN; l += 256) {
        float v = o_logits[i*CN*TN + l];
        slog[l] = g_ok[l >> 2] ? v : -1.f;   // mask dead j: gate (logit>0) then fails
    }
    __syncthreads();
    if (!g_ok[i]) { xout[i*HN + h] = 0.f; return; }
    const float* wr = Wne + ((size_t)it*HN + h)*772 + 768;
    float w40 = wr[0], w41 = wr[1], w42 = wr[2], w43 = wr[3];
    float uh = g_UV[i*512 + h];
    const float* Ep = g_E + (size_t)i*CN*512 + it*HN + h;
    const float NEGINF = __int_as_float(0xff800000);
    float acc = NEGINF;
    #pragma unroll 8
    for (int j = 0; j < CN; j++) {
        float l0 = slog[j*4+0], l1 = slog[j*4+1], l2 = slog[j*4+2], l3 = slog[j*4+3];
        float b0 = l0 > 0.f ? l0*w40 : NEGINF;
        float b1 = l1 > 0.f ? l1*w41 : NEGINF;
        float b2 = l2 > 0.f ? l2*w42 : NEGINF;
        float b3 = l3 > 0.f ? l3*w43 : NEGINF;
        float best = fmaxf(fmaxf(b0, b1), fmaxf(b2, b3));
        float z = uh + g_UV[j*512 + 256 + h] + Ep[(size_t)j*512];
        acc = fmaxf(acc, best + z);          // -inf + finite = -inf
    }
    xout[i*HN + h] = fmaxf(acc, 0.f);
}

// ---------------- launch ---------------------------------------------------
extern "C" void kernel_launch(void* const* d_in, const int* in_sizes, int n_in,
                              void* d_out, int out_size) {
    const float* psf = (const float*)d_in[0];
    const float* pgf = (const float*)d_in[1];
    const float* Wp  = (const float*)d_in[2];
    const float* bp  = (const float*)d_in[3];
    const float* We  = (const float*)d_in[4];
    const float* be  = (const float*)d_in[5];
    const float* Ws  = (const float*)d_in[6];
    const float* bs  = (const float*)d_in[7];
    const float* Wsi = (const float*)d_in[8];
    const float* bsi = (const float*)d_in[9];
    const float* Wel = (const float*)d_in[10];
    const float* bel = (const float*)d_in[11];
    const float* Wee = (const float*)d_in[12];
    const float* bee = (const float*)d_in[13];
    const float* Wne = (const float*)d_in[14];
    const float* bne = (const float*)d_in[15];
    const float* Wc  = (const float*)d_in[16];
    const float* bc  = (const float*)d_in[17];
    const float* Wc2 = (const float*)d_in[18];
    const float* bc2 = (const float*)d_in[19];
    const float* Wgc = (const float*)d_in[20];
    const float* bgc = (const float*)d_in[21];
    const float* Wgp = (const float*)d_in[22];
    const float* bgp = (const float*)d_in[23];
    const float* gw  = (const float*)d_in[24];
    const float* gb  = (const float*)d_in[25];

    float* out       = (float*)d_out;
    float* o_child   = out;                    // 32768
    float* o_geo     = out + 32768;            // 32768
    float* o_sem     = out + 65536;            // 7296
    float* o_semins  = out + 72832;            // 1280
    float* o_exists  = out + 74112;            // 128
    float* o_logits  = out + 74240;            // 65536

    k_gemv_big<<<1024, 256>>>(psf, Wp, bp, pgf, Wgp, bgp);          // 1
    k_heads<<<dim3(CN, 9), 256>>>(We, be, Ws, bs, Wsi, bsi,
                                  o_sem, o_semins, o_exists);       // 2
    k_sgemm<0><<<dim3(16, 4), 256>>>(Wel, bel, nullptr, 0);         // 3  A|B
    k_gemm<<<dim3(128, 4), 256>>>(Wne);                             // 4  E  (profiled)
    k_el<<<CN, 256>>>(Wee, bee, o_logits);                          // 5  logits
    k_sgemm<1><<<dim3(8, 4), 256>>>(Wgc, bgc, nullptr, 0);          // 6  geo GEMM
    k_gn<<<CN, 256>>>(gw, gb, o_geo);                               // 7
    k_sgemm<2><<<dim3(16, 4), 256>>>(Wne, bne, nullptr, 0);         // 8  U|V it=0
    k_reduce<<<CN, 256>>>(o_logits, Wne, 0);                        // 9
    k_sgemm<2><<<dim3(16, 4), 256>>>(Wne, bne, nullptr, 1);         // 10 U|V it=1
    k_reduce<<<CN, 256>>>(o_logits, Wne, 1);                        // 11
    k_sgemm<3><<<dim3(8, 4), 256>>>(Wc, bc, nullptr, 0);            // 12 head1
    k_sgemm<4><<<dim3(8, 4), 256>>>(Wc2, bc2, o_child, 0);          // 13 head2
}

// round 7
// speedup vs baseline: 2.5421x; 1.0599x over previous
#include <cuda_runtime.h>

#define CN 128
#define HN 256
#define TN 4
#define SN 57
#define PN 10
#define BK 16
#define ST 132   // padded smem stride: 528B/row, 16B-aligned for LDS.128 at every k

// ---------------- scratch (device globals; no allocation) ----------------
__device__ float g_cf[CN*HN];          // cf (C,H)
__device__ float g_pg[CN*HN];          // pg (C,H)
__device__ float g_AB[CN*2*HN];        // [A | B+bel]  (C,512)
__device__ float g_gy[CN*HN];          // geo pre-GN
__device__ float g_E [CN*CN*2*HN];     // E (C*C, 512) 33.5MB
__device__ float g_UV[CN*2*HN];        // [U+bne | V] (C,512)
__device__ float g_ch[CN*HN];
__device__ float g_x1[CN*HN];
__device__ float g_x2[CN*HN];
__device__ int   g_ok[CN];

__device__ __forceinline__ float lrelu(float x){ return x > 0.f ? x : 0.01f*x; }

__device__ __forceinline__ float2 fma2(float2 a, float2 b, float2 c) {
    unsigned long long au = *reinterpret_cast<unsigned long long*>(&a);
    unsigned long long bu = *reinterpret_cast<unsigned long long*>(&b);
    unsigned long long cu = *reinterpret_cast<unsigned long long*>(&c);
    unsigned long long du;
    asm("fma.rn.f32x2 %0, %1, %2, %3;" : "=l"(du) : "l"(au), "l"(bu), "l"(cu));
    return *reinterpret_cast<float2*>(&du);
}

// ---------------- 1. big GEMVs: cf and pg (32768 outs each, K=256) --------
__global__ void k_gemv_big(const float* __restrict__ psf, const float* __restrict__ Wp,
                           const float* __restrict__ bp,  const float* __restrict__ pgf,
                           const float* __restrict__ Wgp, const float* __restrict__ bgp) {
    __shared__ float sin_[HN];
    bool second = blockIdx.x >= 512;
    const float* in = second ? pgf : psf;
    const float* W  = second ? Wgp : Wp;
    const float* b  = second ? bgp : bp;
    float* out      = second ? g_pg : g_cf;
    int base = (blockIdx.x & 511) * 64;
    sin_[threadIdx.x] = in[threadIdx.x];
    __syncthreads();
    int warp = threadIdx.x >> 5, lane = threadIdx.x & 31;
    #pragma unroll
    for (int rr = 0; rr < 8; rr++) {
        int r = base + warp*8 + rr;
        const float* wr = W + (size_t)r * HN;
        float s = 0.f;
        #pragma unroll
        for (int q = 0; q < 2; q++) {
            float4 wv = *(const float4*)&wr[lane*4 + 128*q];
            float4 xv = *(const float4*)&sin_[lane*4 + 128*q];
            s += wv.x*xv.x + wv.y*xv.y + wv.z*xv.z + wv.w*xv.w;
        }
        #pragma unroll
        for (int o = 16; o; o >>= 1) s += __shfl_down_sync(0xffffffffu, s, o);
        if (lane == 0) out[r] = lrelu(s + b[r]);
    }
}

// ---------------- 2. generic tiled 32x32x32 SGEMM, M=128, double-buffered --
template<int MODE>
__global__ void __launch_bounds__(256) k_sgemm(const float* __restrict__ W,
                                               const float* __restrict__ b1,
                                               float* __restrict__ out, int it) {
    constexpr int K  = (MODE == 3) ? 768 : 256;
    constexpr int NT = K / 32;
    __shared__ float Xs[2][32][33];
    __shared__ float Ws[2][32][33];
    int tid = threadIdx.x;
    int bn = blockIdx.x, bm = blockIdx.y;
    int r  = tid >> 3, c4 = (tid & 7) * 4;
    int tx = tid & 15, ty = tid >> 4;
    int m0 = bm*32 + r;
    int n0 = bn*32 + r;

    const float* wrow;
    if      (MODE == 0) wrow = W + (n0 < 256 ? (size_t)n0*512 : (size_t)(n0-256)*512 + 256);
    else if (MODE == 1) wrow = W + (size_t)n0*256;
    else if (MODE == 2) wrow = W + ((size_t)it*256 + (n0 & 255))*772 + (n0 >= 256 ? 256 : 0);
    else if (MODE == 3) wrow = W + (size_t)n0*768;
    else                wrow = W + (size_t)n0*256;

    const float* Xbase;
    if      (MODE == 0) Xbase = g_cf;
    else if (MODE == 1) Xbase = g_pg;
    else if (MODE == 2) Xbase = it ? g_x1 : g_cf;
    else if (MODE == 4) Xbase = g_ch;
    else                Xbase = g_cf;

    auto loadX = [&](int kb) -> float4 {
        if (MODE == 3) {
            int g = kb + c4;
            const float* src = (g < 256) ? g_cf : (g < 512 ? g_x1 : g_x2);
            return *(const float4*)(src + (size_t)m0*256 + (g & 255));
        }
        return *(const float4*)(Xbase + (size_t)m0*256 + kb + c4);
    };

    float4 xv = loadX(0);
    float4 wv = *(const float4*)(wrow + c4);
    float a00 = 0.f, a01 = 0.f, a10 = 0.f, a11 = 0.f;

    for (int t = 0; t < NT; t++) {
        int cur = t & 1;
        Xs[cur][c4+0][r] = xv.x; Xs[cur][c4+1][r] = xv.y;
        Xs[cur][c4+2][r] = xv.z; Xs[cur][c4+3][r] = xv.w;
        Ws[cur][c4+0][r] = wv.x; Ws[cur][c4+1][r] = wv.y;
        Ws[cur][c4+2][r] = wv.z; Ws[cur][c4+3][r] = wv.w;
        __syncthreads();
        if (t + 1 < NT) {
            xv = loadX((t+1)*32);
            wv = *(const float4*)(wrow + (t+1)*32 + c4);
        }
        #pragma unroll
        for (int k = 0; k < 32; k++) {
            float ax = Xs[cur][k][ty*2], ay = Xs[cur][k][ty*2+1];
            float bx = Ws[cur][k][tx*2], by = Ws[cur][k][tx*2+1];
            a00 += ax*bx; a01 += ax*by;
            a10 += ay*bx; a11 += ay*by;
        }
    }

    int m = bm*32 + ty*2, n = bn*32 + tx*2;
    float accs[2][2] = {{a00, a01}, {a10, a11}};
    #pragma unroll
    for (int mi = 0; mi < 2; mi++) {
        #pragma unroll
        for (int ni = 0; ni < 2; ni++) {
            int mm = m + mi, nn = n + ni;
            float v = accs[mi][ni];
            if      (MODE == 0) g_AB[mm*512 + nn] = (nn >= 256) ? v + b1[nn-256] : v;
            else if (MODE == 1) g_gy[mm*256 + nn] = v + b1[nn];
            else if (MODE == 2) g_UV[mm*512 + nn] = (nn < 256) ? v + b1[it*256 + nn] : v;
            else if (MODE == 3) g_ch[mm*256 + nn] = lrelu(v + b1[nn]);
            else                out [mm*256 + nn] = lrelu(v + b1[nn]);
        }
    }
}

// ---------------- 3. groupnorm + lrelu epilogue for geo --------------------
__global__ void k_gn(const float* __restrict__ gw, const float* __restrict__ gb,
                     float* __restrict__ outg) {
    int i = blockIdx.x, h = threadIdx.x;
    __shared__ float sy[HN], sm[32], sv[32];
    float s = g_gy[i*HN + h];
    sy[h] = s;
    __syncthreads();
    if (h < 32) {
        float m = 0.f, v = 0.f;
        #pragma unroll
        for (int q = 0; q < 8; q++) { float y = sy[h*8+q]; m += y; v += y*y; }
        m *= 0.125f; v = v*0.125f - m*m;
        sm[h] = m; sv[h] = rsqrtf(v + 1e-5f);
    }
    __syncthreads();
    float xn = (s - sm[h>>3]) * sv[h>>3] * gw[h] + gb[h];
    outg[i*HN + h] = lrelu(xn);
}

// ---------------- 4. small heads: one warp per output, grid (C, 9) --------
__global__ void k_heads(const float* __restrict__ We,  const float* __restrict__ be,
                        const float* __restrict__ Ws,  const float* __restrict__ bs,
                        const float* __restrict__ Wsi, const float* __restrict__ bsi,
                        float* __restrict__ o_sem, float* __restrict__ o_semins,
                        float* __restrict__ o_exists) {
    int i = blockIdx.x;
    int lane = threadIdx.x & 31, warp = threadIdx.x >> 5;
    int o = blockIdx.y * 8 + warp;
    if (o > SN + PN) return;
    const float* w; float bias;
    if (o < SN)           { w = Ws  + o*HN;       bias = bs[o]; }
    else if (o < SN + PN) { w = Wsi + (o-SN)*HN;  bias = bsi[o-SN]; }
    else                  { w = We;               bias = be[0]; }
    float4 x0 = *(const float4*)&g_cf[i*HN + lane*4];
    float4 x1 = *(const float4*)&g_cf[i*HN + 128 + lane*4];
    float4 w0 = *(const float4*)&w[lane*4];
    float4 w1 = *(const float4*)&w[128 + lane*4];
    float s = w0.x*x0.x + w0.y*x0.y + w0.z*x0.z + w0.w*x0.w
            + w1.x*x1.x + w1.y*x1.y + w1.z*x1.z + w1.w*x1.w;
    #pragma unroll
    for (int q = 16; q; q >>= 1) s += __shfl_xor_sync(0xffffffffu, s, q);
    if (lane == 0) {
        s += bias;
        if (o < SN)           o_sem[i*SN + o] = s;
        else if (o < SN + PN) o_semins[i*PN + (o-SN)] = s;
        else { o_exists[i] = s; g_ok[i] = (s > 0.f) ? 1 : 0; }
    }
}

// ---------------- 5. E = el @ W3^T, float4 frags + register pipeline ------
__global__ void __launch_bounds__(256, 2) k_gemm(const float* __restrict__ Wne) {
    int bm = blockIdx.x, bn = blockIdx.y;
    if (g_ok[bm] == 0) return;
    __shared__ float As[2][BK*ST];   // [k][j]
    __shared__ float Bs[2][BK*ST];   // [k][n]
    int tid = threadIdx.x;
    int tx = tid & 15, ty = tid >> 4;

    float4 va[2], vb[2];
    int lm[2], lc[2];
    #pragma unroll
    for (int q = 0; q < 2; q++) { int l = tid + 256*q; lm[q] = l >> 2; lc[q] = (l & 3)*4; }

    auto ld = [&](int kb) {
        #pragma unroll
        for (int q = 0; q < 2; q++) {
            float4 a = *(const float4*)&g_AB[bm*512 + kb + lc[q]];
            float4 b = *(const float4*)&g_AB[lm[q]*512 + 256 + kb + lc[q]];
            va[q].x = lrelu(a.x + b.x);
            va[q].y = lrelu(a.y + b.y);
            va[q].z = lrelu(a.z + b.z);
            va[q].w = lrelu(a.w + b.w);
            int ng = bn*128 + lm[q];
            vb[q] = *(const float4*)&Wne[(size_t)ng*772 + 512 + kb + lc[q]];
        }
    };
    auto sts = [&](int s) {
        #pragma unroll
        for (int q = 0; q < 2; q++) {
            As[s][(lc[q]+0)*ST + lm[q]] = va[q].x;
            As[s][(lc[q]+1)*ST + lm[q]] = va[q].y;
            As[s][(lc[q]+2)*ST + lm[q]] = va[q].z;
            As[s][(lc[q]+3)*ST + lm[q]] = va[q].w;
            Bs[s][(lc[q]+0)*ST + lm[q]] = vb[q].x;
            Bs[s][(lc[q]+1)*ST + lm[q]] = vb[q].y;
            Bs[s][(lc[q]+2)*ST + lm[q]] = vb[q].z;
            Bs[s][(lc[q]+3)*ST + lm[q]] = vb[q].w;
        }
    };

    // accumulators: m = ty*4 + (mi>>2)*64 + (mi&3);  n-pair qn -> tx*4 + (qn>>1)*64 + (qn&1)*2
    float2 c[8][4];
    #pragma unroll
    for (int a = 0; a < 8; a++)
        #pragma unroll
        for (int q = 0; q < 4; q++) c[a][q] = make_float2(0.f, 0.f);

    ld(0);
    sts(0);
    constexpr int NT = HN / BK;
    for (int t = 0; t < NT; t++) {
        int cur = t & 1;
        __syncthreads();
        if (t + 1 < NT) ld((t+1)*BK);

        // register-pipelined inner loop over k
        float4 fa[2][2], fb[2][2];
        fa[0][0] = *(const float4*)&As[cur][ty*4];
        fa[0][1] = *(const float4*)&As[cur][ty*4 + 64];
        fb[0][0] = *(const float4*)&Bs[cur][tx*4];
        fb[0][1] = *(const float4*)&Bs[cur][tx*4 + 64];
        #pragma unroll
        for (int k = 0; k < BK; k++) {
            int pb = k & 1, nb2 = pb ^ 1;
            if (k + 1 < BK) {
                fa[nb2][0] = *(const float4*)&As[cur][(k+1)*ST + ty*4];
                fa[nb2][1] = *(const float4*)&As[cur][(k+1)*ST + ty*4 + 64];
                fb[nb2][0] = *(const float4*)&Bs[cur][(k+1)*ST + tx*4];
                fb[nb2][1] = *(const float4*)&Bs[cur][(k+1)*ST + tx*4 + 64];
            }
            float am[8] = {fa[pb][0].x, fa[pb][0].y, fa[pb][0].z, fa[pb][0].w,
                           fa[pb][1].x, fa[pb][1].y, fa[pb][1].z, fa[pb][1].w};
            float2 bl[4] = {make_float2(fb[pb][0].x, fb[pb][0].y),
                            make_float2(fb[pb][0].z, fb[pb][0].w),
                            make_float2(fb[pb][1].x, fb[pb][1].y),
                            make_float2(fb[pb][1].z, fb[pb][1].w)};
            #pragma unroll
            for (int mi = 0; mi < 8; mi++) {
                float2 a2 = make_float2(am[mi], am[mi]);
                #pragma unroll
                for (int qn = 0; qn < 4; qn++)
                    c[mi][qn] = fma2(a2, bl[qn], c[mi][qn]);
            }
        }
        if (t + 1 < NT) sts(cur ^ 1);
    }
    // epilogue: float4 stores
    #pragma unroll
    for (int mi = 0; mi < 8; mi++) {
        int m = bm*128 + ty*4 + (mi>>2)*64 + (mi&3);
        float* Erow = g_E + (size_t)m*512 + bn*128;
        float4 v0, v1;
        v0.x = c[mi][0].x; v0.y = c[mi][0].y; v0.z = c[mi][1].x; v0.w = c[mi][1].y;
        v1.x = c[mi][2].x; v1.y = c[mi][2].y; v1.z = c[mi][3].x; v1.w = c[mi][3].y;
        *(float4*)&Erow[tx*4]      = v0;
        *(float4*)&Erow[tx*4 + 64] = v1;
    }
}

// ---------------- 6. edge logits only (el recomputed on the fly) ----------
__global__ void __launch_bounds__(256) k_el(const float* __restrict__ Wee,
                                            const float* __restrict__ bee,
                                            float* __restrict__ o_logits) {
    int i = blockIdx.x;
    int t = threadIdx.x;
    int j = t & 127, half = t >> 7;
    __shared__ float sA[256];
    __shared__ float sW[4*256];
    __shared__ float sB[128*33];
    __shared__ float sP[128*8];
    sA[t] = g_AB[i*512 + t];
    #pragma unroll
    for (int l = t; l < 1024; l += 256) sW[l] = Wee[l];
    float acc0 = 0.f, acc1 = 0.f, acc2 = 0.f, acc3 = 0.f;
    for (int c0 = 0; c0 < 256; c0 += 32) {
        __syncthreads();
        #pragma unroll
        for (int idx = t; idx < 1024; idx += 256) {
            int jj = idx >> 3, f4 = (idx & 7) * 4;
            float4 v = *(const float4*)&g_AB[jj*512 + 256 + c0 + f4];
            sB[jj*33 + f4+0] = v.x; sB[jj*33 + f4+1] = v.y;
            sB[jj*33 + f4+2] = v.z; sB[jj*33 + f4+3] = v.w;
        }
        __syncthreads();
        int h0 = half*16;
        #pragma unroll
        for (int hh = 0; hh < 16; hh++) {
            int h = h0 + hh;
            float e = lrelu(sA[c0+h] + sB[j*33 + h]);
            acc0 += e * sW[        c0+h];
            acc1 += e * sW[256  + c0+h];
            acc2 += e * sW[512  + c0+h];
            acc3 += e * sW[768  + c0+h];
        }
    }
    sP[(j*2+half)*4 + 0] = acc0;
    sP[(j*2+half)*4 + 1] = acc1;
    sP[(j*2+half)*4 + 2] = acc2;
    sP[(j*2+half)*4 + 3] = acc3;
    __syncthreads();
    if (t < 128) {
        float4 o;
        o.x = sP[t*8+0] + sP[t*8+4] + bee[0];
        o.y = sP[t*8+1] + sP[t*8+5] + bee[1];
        o.z = sP[t*8+2] + sP[t*8+6] + bee[2];
        o.w = sP[t*8+3] + sP[t*8+7] + bee[3];
        *(float4*)&o_logits[(i*128 + t)*4] = o;
    }
}

// ---------------- 7. masked max-reduction over (j,t), branchless ----------
__global__ void k_reduce(const float* __restrict__ o_logits,
                         const float* __restrict__ Wne, int it) {
    int i = blockIdx.x, h = threadIdx.x;
    float* xout = (it == 0) ? g_x1 : g_x2;
    __shared__ float slog[CN*TN];
    #pragma unroll
    for (int l = h; l < CN*TN; l += 256) {
        float v = o_logits[i*CN*TN + l];
        slog[l] = g_ok[l >> 2] ? v : -1.f;   // mask dead j: gate (logit>0) then fails
    }
    __syncthreads();
    if (!g_ok[i]) { xout[i*HN + h] = 0.f; return; }
    const float* wr = Wne + ((size_t)it*HN + h)*772 + 768;
    float w40 = wr[0], w41 = wr[1], w42 = wr[2], w43 = wr[3];
    float uh = g_UV[i*512 + h];
    const float* Ep = g_E + (size_t)i*CN*512 + it*HN + h;
    const float NEGINF = __int_as_float(0xff800000);
    float acc = NEGINF;
    #pragma unroll 8
    for (int j = 0; j < CN; j++) {
        float l0 = slog[j*4+0], l1 = slog[j*4+1], l2 = slog[j*4+2], l3 = slog[j*4+3];
        float b0 = l0 > 0.f ? l0*w40 : NEGINF;
        float b1 = l1 > 0.f ? l1*w41 : NEGINF;
        float b2 = l2 > 0.f ? l2*w42 : NEGINF;
        float b3 = l3 > 0.f ? l3*w43 : NEGINF;
        float best = fmaxf(fmaxf(b0, b1), fmaxf(b2, b3));
        float z = uh + g_UV[j*512 + 256 + h] + Ep[(size_t)j*512];
        acc = fmaxf(acc, best + z);          // -inf + finite = -inf
    }
    xout[i*HN + h] = fmaxf(acc, 0.f);
}

// ---------------- launch ---------------------------------------------------
extern "C" void kernel_launch(void* const* d_in, const int* in_sizes, int n_in,
                              void* d_out, int out_size) {
    const float* psf = (const float*)d_in[0];
    const float* pgf = (const float*)d_in[1];
    const float* Wp  = (const float*)d_in[2];
    const float* bp  = (const float*)d_in[3];
    const float* We  = (const float*)d_in[4];
    const float* be  = (const float*)d_in[5];
    const float* Ws  = (const float*)d_in[6];
    const float* bs  = (const float*)d_in[7];
    const float* Wsi = (const float*)d_in[8];
    const float* bsi = (const float*)d_in[9];
    const float* Wel = (const float*)d_in[10];
    const float* bel = (const float*)d_in[11];
    const float* Wee = (const float*)d_in[12];
    const float* bee = (const float*)d_in[13];
    const float* Wne = (const float*)d_in[14];
    const float* bne = (const float*)d_in[15];
    const float* Wc  = (const float*)d_in[16];
    const float* bc  = (const float*)d_in[17];
    const float* Wc2 = (const float*)d_in[18];
    const float* bc2 = (const float*)d_in[19];
    const float* Wgc = (const float*)d_in[20];
    const float* bgc = (const float*)d_in[21];
    const float* Wgp = (const float*)d_in[22];
    const float* bgp = (const float*)d_in[23];
    const float* gw  = (const float*)d_in[24];
    const float* gb  = (const float*)d_in[25];

    float* out       = (float*)d_out;
    float* o_child   = out;                    // 32768
    float* o_geo     = out + 32768;            // 32768
    float* o_sem     = out + 65536;            // 7296
    float* o_semins  = out + 72832;            // 1280
    float* o_exists  = out + 74112;            // 128
    float* o_logits  = out + 74240;            // 65536

    k_gemv_big<<<1024, 256>>>(psf, Wp, bp, pgf, Wgp, bgp);          // 1
    k_heads<<<dim3(CN, 9), 256>>>(We, be, Ws, bs, Wsi, bsi,
                                  o_sem, o_semins, o_exists);       // 2
    k_sgemm<0><<<dim3(16, 4), 256>>>(Wel, bel, nullptr, 0);         // 3  A|B
    k_gemm<<<dim3(128, 4), 256>>>(Wne);                             // 4  E  (profiled)
    k_el<<<CN, 256>>>(Wee, bee, o_logits);                          // 5  logits
    k_sgemm<1><<<dim3(8, 4), 256>>>(Wgc, bgc, nullptr, 0);          // 6  geo GEMM
    k_gn<<<CN, 256>>>(gw, gb, o_geo);                               // 7
    k_sgemm<2><<<dim3(16, 4), 256>>>(Wne, bne, nullptr, 0);         // 8  U|V it=0
    k_reduce<<<CN, 256>>>(o_logits, Wne, 0);                        // 9
    k_sgemm<2><<<dim3(16, 4), 256>>>(Wne, bne, nullptr, 1);         // 10 U|V it=1
    k_reduce<<<CN, 256>>>(o_logits, Wne, 1);                        // 11
    k_sgemm<3><<<dim3(8, 4), 256>>>(Wc, bc, nullptr, 0);            // 12 head1
    k_sgemm<4><<<dim3(8, 4), 256>>>(Wc2, bc2, o_child, 0);          // 13 head2
}